// round 14
// baseline (speedup 1.0000x reference)
#include <cuda_runtime.h>
#include <cuda_fp16.h>
#include <math.h>

#define NN 8192
#define DD 256
#define KK 16
#define KSEL 17
#define RS28 28           // refine candidates per row
#define MS 24             // local streaming top-M per row
#define BM 64
#define BN 64
#define NTILE 128         // 8192/64
#define JTS 8             // thresh-pass sample tiles (512 cols)
#define MST 20            // thresh-pass top-M -> tau
#define RSB 264           // smem row stride in fp16 elements (528B)
#define CAP 1024
#define TCAP 512          // per-tile transpose staging capacity
#define SCAP 384          // per-row buffer scan cap in sel
#define STH 1024          // screen kernel threads (32 warps -> 8/SMSP)
#define ULLINF 0xFFFFFFFFFFFFFFFFull

__device__ float g_sq[NN];
__device__ float g_tau[NN];
__device__ __half2 g_fh16[NN * DD / 2];
__device__ int g_bcnt[NN];
__device__ unsigned long long g_buf[(size_t)NN * CAP];
__device__ unsigned long long g_loc[(size_t)NN * MS];
__device__ unsigned long long g_cand[NN * RS28];
__device__ unsigned long long g_best[NN * KSEL];

__device__ __forceinline__ unsigned smem_u32(const void* p) {
    unsigned a;
    asm("{ .reg .u64 t; cvta.to.shared.u64 t, %1; cvt.u32.u64 %0, t; }" : "=r"(a) : "l"(p));
    return a;
}
__device__ __forceinline__ unsigned mono(float f) {
    unsigned u = __float_as_uint(f);
    return (u & 0x80000000u) ? ~u : (u | 0x80000000u);
}
__device__ __forceinline__ float unmono(unsigned u) {
    return __uint_as_float((u & 0x80000000u) ? (u ^ 0x80000000u) : ~u);
}

#define CP16(dst, src) asm volatile("cp.async.cg.shared.global [%0], [%1], 16;" :: "r"(dst), "l"(src) : "memory")
#define CP_COMMIT()    asm volatile("cp.async.commit_group;" ::: "memory")
#define CP_WAIT(n)     asm volatile("cp.async.wait_group %0;" :: "n"(n) : "memory")
#define LDSM_X4(r0, r1, r2, r3, a) \
    asm volatile("ldmatrix.sync.aligned.m8n8.x4.shared.b16 {%0,%1,%2,%3}, [%4];" \
        : "=r"(r0), "=r"(r1), "=r"(r2), "=r"(r3) : "r"(a))
#define LDSM_X2(r0, r1, a) \
    asm volatile("ldmatrix.sync.aligned.m8n8.x2.shared.b16 {%0,%1}, [%2];" \
        : "=r"(r0), "=r"(r1) : "r"(a))
#define MMA_F16(d0, d1, a0, a1, a2, a3, b0, b1) \
    asm volatile("mma.sync.aligned.m16n8k16.row.col.f16.f16.f16.f16 " \
        "{%0,%1},{%2,%3,%4,%5},{%6,%7},{%0,%1};" \
        : "+r"(d0), "+r"(d1) \
        : "r"(a0), "r"(a1), "r"(a2), "r"(a3), "r"(b0), "r"(b1))

// ---------------- Kernel A: norms + fp16 convert + counter reset ----------------
__global__ void sq_kernel(const float* __restrict__ feats) {
    int gw = (blockIdx.x * blockDim.x + threadIdx.x) >> 5;
    int lane = threadIdx.x & 31;
    if (gw >= NN) return;
    const float4* rowp = (const float4*)(feats + (size_t)gw * DD);
    float4 a = rowp[lane];
    float4 b = rowp[lane + 32];
    float s = a.x*a.x + a.y*a.y + a.z*a.z + a.w*a.w
            + b.x*b.x + b.y*b.y + b.z*b.z + b.w*b.w;
    #pragma unroll
    for (int o = 16; o; o >>= 1) s += __shfl_xor_sync(0xffffffffu, s, o);
    if (lane == 0) { g_sq[gw] = s; g_bcnt[gw] = 0; }
    __half2* dst = g_fh16 + (size_t)gw * (DD / 2);
    dst[lane * 2]          = __floats2half2_rn(a.x, a.y);
    dst[lane * 2 + 1]      = __floats2half2_rn(a.z, a.w);
    dst[64 + lane * 2]     = __floats2half2_rn(b.x, b.y);
    dst[64 + lane * 2 + 1] = __floats2half2_rn(b.z, b.w);
}

// dummy: occupies launch slot #3 so screen_kernel (launch #4) gets ncu-profiled
__global__ void dummy_kernel() {}

// ---------------- Kernel T: sample 512 cols -> per-row tau (20th-smallest key) ----------------
struct SmemT {
    __half A[BM][RSB];
    __half B[2][BN][RSB];
    float sqB[2][BN];
    float thr[BM];
    int   cnt[BM];
    unsigned long long best[BM][MST];
    unsigned long long cand[BM][BN];
};

__device__ __forceinline__ void prefetch_BT(SmemT& sm, int s, int j0, int tid) {
    #pragma unroll
    for (int t = 0; t < 8; ++t) {
        int idx = t * 256 + tid;
        int r = idx >> 5, ch = idx & 31;
        unsigned dst = smem_u32(&sm.B[s][r][ch * 8]);
        const void* src = (const char*)g_fh16 + (((size_t)(j0 + r) * DD) + ch * 8) * 2;
        CP16(dst, src);
    }
    if (tid < 16) {
        unsigned dst = smem_u32(&sm.sqB[s][tid * 4]);
        const void* src = g_sq + j0 + tid * 4;
        CP16(dst, src);
    }
}

__global__ void __launch_bounds__(256, 1) thresh_kernel() {
    extern __shared__ char raw[];
    SmemT& sm = *reinterpret_cast<SmemT*>(raw);
    const int tid = threadIdx.x;
    const int lane = tid & 31;
    const int w = tid >> 5;
    const int wr = w >> 1;
    const int wc = w & 1;
    const int i0 = blockIdx.x * BM;

    #pragma unroll
    for (int t = 0; t < 8; ++t) {
        int idx = t * 256 + tid;
        int r = idx >> 5, ch = idx & 31;
        unsigned dst = smem_u32(&sm.A[r][ch * 8]);
        const void* src = (const char*)g_fh16 + (((size_t)(i0 + r) * DD) + ch * 8) * 2;
        CP16(dst, src);
    }
    CP_COMMIT();
    prefetch_BT(sm, 0, 0, tid);
    CP_COMMIT();

    if (tid < BM) {
        sm.thr[tid] = __int_as_float(0x7f800000);
        sm.cnt[tid] = 0;
        #pragma unroll
        for (int t = 0; t < MST; ++t) sm.best[tid][t] = 0xFF800000FFFFFFFFull;
    }

    const unsigned aAddr = smem_u32(&sm.A[wr * 16 + (lane & 15)][0]) + ((lane >> 4) << 4);
    const int rowB = wc * 32 + ((lane >> 4) << 3) + (lane & 7);
    const unsigned bColOff = ((lane >> 3) & 1) << 4;
    unsigned bAddrBase[2];
    bAddrBase[0] = smem_u32(&sm.B[0][rowB][0]) + bColOff;
    bAddrBase[1] = smem_u32(&sm.B[1][rowB][0]) + bColOff;

    const int R0 = wr * 16 + (lane >> 2);
    const int R1 = R0 + 8;
    const int cBase = wc * 32 + 2 * (lane & 3);

    for (int jt = 0; jt < JTS; ++jt) {
        const int s = jt & 1;
        const int j0 = jt * BN;

        if (jt + 1 < JTS) {
            prefetch_BT(sm, s ^ 1, (jt + 1) * BN, tid);
            CP_COMMIT();
            CP_WAIT(1);
        } else {
            CP_WAIT(0);
        }
        __syncthreads();

        unsigned acc[4][2];
        #pragma unroll
        for (int nt = 0; nt < 4; ++nt) { acc[nt][0] = 0u; acc[nt][1] = 0u; }

        const unsigned bA = bAddrBase[s];
        #pragma unroll
        for (int ks = 0; ks < 16; ++ks) {
            unsigned a0, a1, a2, a3;
            LDSM_X4(a0, a1, a2, a3, aAddr + ks * 32);
            unsigned p00, p01, p10, p11, q00, q01, q10, q11;
            LDSM_X4(p00, p01, p10, p11, bA + ks * 32);
            LDSM_X4(q00, q01, q10, q11, bA + 16 * (RSB * 2) + ks * 32);
            MMA_F16(acc[0][0], acc[0][1], a0, a1, a2, a3, p00, p01);
            MMA_F16(acc[1][0], acc[1][1], a0, a1, a2, a3, p10, p11);
            MMA_F16(acc[2][0], acc[2][1], a0, a1, a2, a3, q00, q01);
            MMA_F16(acc[3][0], acc[3][1], a0, a1, a2, a3, q10, q11);
        }

        const float t0 = sm.thr[R0];
        const float t1 = sm.thr[R1];
        const float* sq = sm.sqB[s];
        #pragma unroll
        for (int nt = 0; nt < 4; ++nt) {
            const int c = cBase + nt * 8;
            float2 f0 = __half22float2(*(__half2*)&acc[nt][0]);
            float2 f1 = __half22float2(*(__half2*)&acc[nt][1]);
            float v00 = fmaf(-2.f, f0.x, sq[c]);
            float v01 = fmaf(-2.f, f0.y, sq[c + 1]);
            float v10 = fmaf(-2.f, f1.x, sq[c]);
            float v11 = fmaf(-2.f, f1.y, sq[c + 1]);
            if (v00 < t0) { int p = atomicAdd(&sm.cnt[R0], 1);
                sm.cand[R0][p] = ((unsigned long long)mono(v00) << 32) | (unsigned)(j0 + c); }
            if (v01 < t0) { int p = atomicAdd(&sm.cnt[R0], 1);
                sm.cand[R0][p] = ((unsigned long long)mono(v01) << 32) | (unsigned)(j0 + c + 1); }
            if (v10 < t1) { int p = atomicAdd(&sm.cnt[R1], 1);
                sm.cand[R1][p] = ((unsigned long long)mono(v10) << 32) | (unsigned)(j0 + c); }
            if (v11 < t1) { int p = atomicAdd(&sm.cnt[R1], 1);
                sm.cand[R1][p] = ((unsigned long long)mono(v11) << 32) | (unsigned)(j0 + c + 1); }
        }
        __syncthreads();

        if (tid < BM) {
            int n = sm.cnt[tid];
            if (n) {
                sm.cnt[tid] = 0;
                unsigned long long* bl = sm.best[tid];
                for (int q = 0; q < n; ++q) {
                    unsigned long long key = sm.cand[tid][q];
                    if (key < bl[MST - 1]) {
                        int p = MST - 1;
                        while (p > 0 && bl[p - 1] > key) { bl[p] = bl[p - 1]; --p; }
                        bl[p] = key;
                    }
                }
                sm.thr[tid] = unmono((unsigned)(bl[MST - 1] >> 32));
            }
        }
    }

    if (tid < BM)
        g_tau[i0 + tid] = unmono((unsigned)(sm.best[tid][MST - 1] >> 32));
}

// ---------------- Kernel S: cyclic symmetric screen, 1024 threads (8 warps/SMSP) ----------------
struct SmemS {
    __half A[BM][RSB];
    __half B[2][BN][RSB];
    float sqB[2][BN], tauB[2][BN];
    float sqA[BM];
    float thr[BM];
    int   cnt[BM];
    unsigned long long best[BM][MS];
    unsigned long long cand[BM][BN];
    unsigned long long tval[TCAP];
    unsigned char tcol[TCAP];
    int tcnt;
};

__device__ __forceinline__ void prefetch_BS(SmemS& sm, int s, int j0, int tid) {
    #pragma unroll
    for (int t = 0; t < 2; ++t) {
        int idx = t * STH + tid;
        int r = idx >> 5, ch = idx & 31;
        unsigned dst = smem_u32(&sm.B[s][r][ch * 8]);
        const void* src = (const char*)g_fh16 + (((size_t)(j0 + r) * DD) + ch * 8) * 2;
        CP16(dst, src);
    }
    if (tid < 16) {
        unsigned dst = smem_u32(&sm.sqB[s][tid * 4]);
        CP16(dst, (const void*)(g_sq + j0 + tid * 4));
    } else if (tid < 32) {
        int t = tid - 16;
        unsigned dst = smem_u32(&sm.tauB[s][t * 4]);
        CP16(dst, (const void*)(g_tau + j0 + t * 4));
    }
}

__global__ void __launch_bounds__(STH, 1) screen_kernel() {
    extern __shared__ char raw[];
    SmemS& sm = *reinterpret_cast<SmemS*>(raw);
    const int tid = threadIdx.x;
    const int lane = tid & 31;
    const int w = tid >> 5;            // 0..31
    const int wr = w >> 3;             // 0..3 -> 16-row strip
    const int wc = w & 7;              // 0..7 -> 8-col strip
    const int it = blockIdx.x;
    const int i0 = it * BM;
    const int NT = (it < 64) ? 65 : 64;

    #pragma unroll
    for (int t = 0; t < 2; ++t) {
        int idx = t * STH + tid;
        int r = idx >> 5, ch = idx & 31;
        unsigned dst = smem_u32(&sm.A[r][ch * 8]);
        const void* src = (const char*)g_fh16 + (((size_t)(i0 + r) * DD) + ch * 8) * 2;
        CP16(dst, src);
    }
    CP_COMMIT();
    prefetch_BS(sm, 0, i0, tid);
    CP_COMMIT();

    if (tid < BM) {
        sm.sqA[tid] = g_sq[i0 + tid];
        sm.thr[tid] = __int_as_float(0x7f800000);
        sm.cnt[tid] = 0;
        #pragma unroll
        for (int t = 0; t < MS; ++t) sm.best[tid][t] = 0xFF800000FFFFFFFFull;
    }
    if (tid == 0) sm.tcnt = 0;

    // fragment addresses: warp tile 16 rows x 8 cols
    const unsigned aAddr = smem_u32(&sm.A[wr * 16 + (lane & 15)][0]) + ((lane >> 4) << 4);
    const int rowB = wc * 8 + (lane & 7);
    const unsigned bColOff = ((lane >> 3) & 1) << 4;    // lanes 8-15 -> k+8 half
    unsigned bAddrBase[2];
    bAddrBase[0] = smem_u32(&sm.B[0][rowB][0]) + bColOff;
    bAddrBase[1] = smem_u32(&sm.B[1][rowB][0]) + bColOff;

    const int R0 = wr * 16 + (lane >> 2);
    const int R1 = R0 + 8;
    const int cBase = wc * 8 + 2 * (lane & 3);

    for (int t = 0; t < NT; ++t) {
        const int s = t & 1;
        const int jt = (it + t) & (NTILE - 1);
        const int j0 = jt * BN;
        const bool offdiag = (t != 0);

        if (t + 1 < NT) {
            prefetch_BS(sm, s ^ 1, ((it + t + 1) & (NTILE - 1)) * BN, tid);
            CP_COMMIT();
            CP_WAIT(1);
        } else {
            CP_WAIT(0);
        }
        __syncthreads();

        unsigned acc0 = 0u, acc1 = 0u;

        const unsigned bA = bAddrBase[s];
        #pragma unroll
        for (int ks = 0; ks < 16; ++ks) {
            unsigned a0, a1, a2, a3;
            LDSM_X4(a0, a1, a2, a3, aAddr + ks * 32);
            unsigned b0, b1;
            LDSM_X2(b0, b1, bA + ks * 32);
            MMA_F16(acc0, acc1, a0, a1, a2, a3, b0, b1);
        }

        // --- epilogue: 4 elements/thread ---
        const float t0 = sm.thr[R0];
        const float t1 = sm.thr[R1];
        const float sqa0 = sm.sqA[R0];
        const float sqa1 = sm.sqA[R1];
        const float* sq = sm.sqB[s];
        const float* tb = sm.tauB[s];

        float sv[4];
        {
            float2 f0 = __half22float2(*(__half2*)&acc0);   // row R0: cBase, cBase+1
            float2 f1 = __half22float2(*(__half2*)&acc1);   // row R1: cBase, cBase+1
            sv[0] = f0.x; sv[1] = f0.y; sv[2] = f1.x; sv[3] = f1.y;
        }
        float vl[4], wt[4];
        unsigned mL = 0, mT = 0;
        #pragma unroll
        for (int e = 0; e < 4; ++e) {
            const bool hi = (e >= 2);
            const int col = cBase + (e & 1);
            vl[e] = fmaf(-2.f, sv[e], sq[col]);
            wt[e] = fmaf(-2.f, sv[e], hi ? sqa1 : sqa0);
            if (vl[e] < (hi ? t1 : t0)) mL |= 1u << e;
            if (wt[e] <= tb[col])       mT |= 1u << e;
        }
        if (!offdiag) mT = 0;
        if (mL) {
            #pragma unroll
            for (int e = 0; e < 4; ++e) if (mL & (1u << e)) {
                const int row = (e >= 2) ? R1 : R0;
                const int col = cBase + (e & 1);
                int p = atomicAdd(&sm.cnt[row], 1);
                sm.cand[row][p] = ((unsigned long long)mono(vl[e]) << 32) | (unsigned)(j0 + col);
            }
        }
        if (mT) {
            #pragma unroll
            for (int e = 0; e < 4; ++e) if (mT & (1u << e)) {
                const int row = (e >= 2) ? R1 : R0;
                const int col = cBase + (e & 1);
                unsigned long long val = ((unsigned long long)mono(wt[e]) << 32) | (unsigned)(i0 + row);
                int p = atomicAdd(&sm.tcnt, 1);
                if (p < TCAP) { sm.tval[p] = val; sm.tcol[p] = (unsigned char)col; }
                else { int g = atomicAdd(&g_bcnt[j0 + col], 1);
                       if (g < CAP) g_buf[(size_t)(j0 + col) * CAP + g] = val; }
            }
        }
        __syncthreads();

        // cooperative drain of staged transpose appends
        {
            int n = sm.tcnt;
            if (n > TCAP) n = TCAP;
            for (int q = tid; q < n; q += STH) {
                int trow = j0 + (int)sm.tcol[q];
                int p = atomicAdd(&g_bcnt[trow], 1);
                if (p < CAP) g_buf[(size_t)trow * CAP + p] = sm.tval[q];
            }
        }
        // local flush (tid<BM) concurrent with the drain
        if (tid < BM) {
            int n = sm.cnt[tid];
            if (n) {
                sm.cnt[tid] = 0;
                unsigned long long* bl = sm.best[tid];
                for (int q = 0; q < n; ++q) {
                    unsigned long long key = sm.cand[tid][q];
                    if (key < bl[MS - 1]) {
                        int p = MS - 1;
                        while (p > 0 && bl[p - 1] > key) { bl[p] = bl[p - 1]; --p; }
                        bl[p] = key;
                    }
                }
                sm.thr[tid] = unmono((unsigned)(bl[MS - 1] >> 32));
            }
        }
        __syncthreads();
        if (tid == 0) sm.tcnt = 0;
    }
    __syncthreads();

    for (int idx = tid; idx < BM * MS; idx += STH) {
        int r = idx / MS, t = idx % MS;
        g_loc[(size_t)(i0 + r) * MS + t] = sm.best[r][t];
    }
}

// ---------------- Kernel L: warp-per-row merge of local top-24 + buffer -> top-28 ----------------
__global__ void __launch_bounds__(256) sel_kernel() {
    __shared__ unsigned long long ch[8][32][13];
    const int lane = threadIdx.x & 31;
    const int w = threadIdx.x >> 5;
    const int row = blockIdx.x * 8 + w;

    unsigned long long* my = ch[w][lane];
    int len = 0;
    if (lane < MS) { my[0] = g_loc[(size_t)row * MS + lane]; len = 1; }
    int cnt = g_bcnt[row];
    if (cnt > SCAP) cnt = SCAP;
    const unsigned long long* bp = g_buf + (size_t)row * CAP;
    for (int q = lane; q < cnt; q += 32) {
        unsigned long long key = bp[q];
        int p = len++;
        while (p > 0 && my[p - 1] > key) { my[p] = my[p - 1]; --p; }
        my[p] = key;
    }
    __syncwarp();

    int ptr = 0;
    for (int sel = 0; sel < RS28; ++sel) {
        unsigned long long h = (ptr < len) ? my[ptr] : ULLINF;
        unsigned long long M = h;
        #pragma unroll
        for (int o = 16; o; o >>= 1) {
            unsigned long long v = __shfl_xor_sync(0xffffffffu, M, o);
            M = (v < M) ? v : M;
        }
        unsigned b = __ballot_sync(0xffffffffu, h == M);
        if (lane == (__ffs(b) - 1)) ++ptr;
        if (lane == 0) g_cand[(size_t)row * RS28 + sel] = M;
    }
}

// ---------------- Kernel R: exact fp32 refine of 28 survivors -> exact top-17 ----------------
__global__ void refine_kernel(const float* __restrict__ feats) {
    int row = (blockIdx.x * blockDim.x + threadIdx.x) >> 5;
    int lane = threadIdx.x & 31;
    if (row >= NN) return;

    const float* base = feats + (size_t)row * DD;
    float4 a0 = *(const float4*)(base + lane * 4);
    float4 a1 = *(const float4*)(base + 128 + lane * 4);
    float own[8] = {a0.x, a0.y, a0.z, a0.w, a1.x, a1.y, a1.z, a1.w};

    unsigned long long mykey = ULLINF;

    #pragma unroll 4
    for (int t = 0; t < RS28; ++t) {
        unsigned long long ak = g_cand[(size_t)row * RS28 + t];
        int j = (ak == ULLINF) ? 0 : (int)(unsigned)(ak & 0xffffffffull);
        const float* nb = feats + (size_t)j * DD;
        float4 b0 = *(const float4*)(nb + lane * 4);
        float4 b1 = *(const float4*)(nb + 128 + lane * 4);
        float p = own[0]*b0.x + own[1]*b0.y + own[2]*b0.z + own[3]*b0.w
                + own[4]*b1.x + own[5]*b1.y + own[6]*b1.z + own[7]*b1.w;
        #pragma unroll
        for (int o = 16; o; o >>= 1) p += __shfl_xor_sync(0xffffffffu, p, o);
        float val = fmaf(-2.f, p, g_sq[j]);
        unsigned long long key = (ak == ULLINF) ? ULLINF
                               : (((unsigned long long)mono(val) << 32) | (unsigned)j);
        if (lane == t) mykey = key;
    }

    int rank = 0;
    #pragma unroll
    for (int s = 0; s < RS28; ++s) {
        unsigned long long ok = __shfl_sync(0xffffffffu, mykey, s);
        rank += (ok < mykey);
    }
    if (lane < RS28 && rank < KSEL && mykey != ULLINF)
        g_best[(size_t)row * KSEL + rank] = mykey;
}

// ---------------- Kernel C: mutual mask + sparse softmax + AV + residual + normalize ----------------
__global__ void fuse_kernel(const float* __restrict__ feats, float* __restrict__ out) {
    int gw = (blockIdx.x * blockDim.x + threadIdx.x) >> 5;
    int lane = threadIdx.x & 31;
    if (gw >= NN) return;
    const int row = gw;
    const float* base = feats + (size_t)row * DD;
    float4 a0 = *(const float4*)(base + lane * 4);
    float4 a1 = *(const float4*)(base + 128 + lane * 4);
    float own[8] = {a0.x, a0.y, a0.z, a0.w, a1.x, a1.y, a1.z, a1.w};

    int my_nbr = -1;
    int cnt = 0;
    #pragma unroll
    for (int t = 0; t < KSEL; ++t) {
        unsigned long long key = g_best[(size_t)row * KSEL + t];
        int j = (int)(unsigned)(key & 0xffffffffull);
        if (j != row && cnt < KK) {
            if (cnt == lane) my_nbr = j;
            cnt++;
        }
    }

    bool found = false;
    if (lane < KK && my_nbr >= 0) {
        #pragma unroll
        for (int t = 0; t < KSEL; ++t) {
            unsigned long long key = g_best[(size_t)my_nbr * KSEL + t];
            if ((int)(unsigned)(key & 0xffffffffull) == row) found = true;
        }
    }
    unsigned mmask = __ballot_sync(0xffffffffu, found) & 0xffffu;

    float m = 1.0f, Z = 1.0f;
    float acc[8];
    #pragma unroll
    for (int e = 0; e < 8; ++e) acc[e] = own[e];

    for (int l = 0; l < KK; ++l) {
        if (!((mmask >> l) & 1u)) continue;
        int j = __shfl_sync(0xffffffffu, my_nbr, l);
        const float* nb = feats + (size_t)j * DD;
        float4 b0 = *(const float4*)(nb + lane * 4);
        float4 b1 = *(const float4*)(nb + 128 + lane * 4);
        float v[8] = {b0.x, b0.y, b0.z, b0.w, b1.x, b1.y, b1.z, b1.w};
        float p = 0.f;
        #pragma unroll
        for (int e = 0; e < 8; ++e) p = fmaf(own[e], v[e], p);
        #pragma unroll
        for (int o = 16; o; o >>= 1) p += __shfl_xor_sync(0xffffffffu, p, o);
        if (p > m) {
            float f = expf(m - p);
            Z = Z * f + 1.0f;
            #pragma unroll
            for (int e = 0; e < 8; ++e) acc[e] = fmaf(acc[e], f, v[e]);
            m = p;
        } else {
            float wgt = expf(p - m);
            Z += wgt;
            #pragma unroll
            for (int e = 0; e < 8; ++e) acc[e] = fmaf(wgt, v[e], acc[e]);
        }
    }

    float invZ = 1.0f / Z;
    float fcm[8];
    float ss = 0.f;
    #pragma unroll
    for (int e = 0; e < 8; ++e) {
        fcm[e] = fmaf(acc[e], invZ, own[e]);
        ss = fmaf(fcm[e], fcm[e], ss);
    }
    #pragma unroll
    for (int o = 16; o; o >>= 1) ss += __shfl_xor_sync(0xffffffffu, ss, o);
    float inv = 1.0f / fmaxf(sqrtf(ss), 1e-12f);

    float* op = out + (size_t)row * DD;
    *(float4*)(op + lane * 4)       = make_float4(fcm[0]*inv, fcm[1]*inv, fcm[2]*inv, fcm[3]*inv);
    *(float4*)(op + 128 + lane * 4) = make_float4(fcm[4]*inv, fcm[5]*inv, fcm[6]*inv, fcm[7]*inv);
}

// ---------------- launch ----------------
extern "C" void kernel_launch(void* const* d_in, const int* in_sizes, int n_in,
                              void* d_out, int out_size) {
    const float* feats = (const float*)d_in[0];
    float* out = (float*)d_out;
    (void)in_sizes; (void)n_in; (void)out_size;

    cudaFuncSetAttribute(thresh_kernel, cudaFuncAttributeMaxDynamicSharedMemorySize,
                         (int)sizeof(SmemT));
    cudaFuncSetAttribute(screen_kernel, cudaFuncAttributeMaxDynamicSharedMemorySize,
                         (int)sizeof(SmemS));

    sq_kernel<<<NN / 8, 256>>>(feats);
    thresh_kernel<<<NN / BM, 256, sizeof(SmemT)>>>();
    dummy_kernel<<<1, 32>>>();
    screen_kernel<<<NTILE, STH, sizeof(SmemS)>>>();
    sel_kernel<<<NN / 8, 256>>>();
    refine_kernel<<<NN / 8, 256>>>(feats);
    fuse_kernel<<<NN / 8, 256>>>(feats, out);
}

// round 15
// speedup vs baseline: 1.3767x; 1.3767x over previous
#include <cuda_runtime.h>
#include <cuda_fp16.h>
#include <math.h>

#define NN 8192
#define DD 256
#define KK 16
#define KSEL 17
#define RS28 28           // refine candidates per row
#define MS 24             // local streaming top-M per row (per half)
#define BM 64
#define BN 64
#define NTILE 128         // 8192/64
#define JTS 8             // thresh-pass sample tiles (512 cols)
#define MST 20            // thresh-pass top-M -> tau
#define RSB 264           // smem row stride in fp16 elements (528B)
#define CAP 1024
#define TCAP 512          // per-tile transpose staging capacity
#define CCAP 16           // per-row per-tile local candidate cap (overflow -> g_buf)
#define SCAP 384          // per-row buffer scan cap in sel
#define STH 512           // screen threads (16 warps), 2 CTAs/SM
#define ULLINF 0xFFFFFFFFFFFFFFFFull

__device__ float g_sq[NN];
__device__ float g_tau[NN];
__device__ __half2 g_fh16[NN * DD / 2];
__device__ int g_bcnt[NN];
__device__ unsigned long long g_buf[(size_t)NN * CAP];
__device__ unsigned long long g_loc[(size_t)NN * 2 * MS];
__device__ unsigned long long g_cand[NN * RS28];
__device__ unsigned long long g_best[NN * KSEL];

__device__ __forceinline__ unsigned smem_u32(const void* p) {
    unsigned a;
    asm("{ .reg .u64 t; cvta.to.shared.u64 t, %1; cvt.u32.u64 %0, t; }" : "=r"(a) : "l"(p));
    return a;
}
__device__ __forceinline__ unsigned mono(float f) {
    unsigned u = __float_as_uint(f);
    return (u & 0x80000000u) ? ~u : (u | 0x80000000u);
}
__device__ __forceinline__ float unmono(unsigned u) {
    return __uint_as_float((u & 0x80000000u) ? (u ^ 0x80000000u) : ~u);
}

#define CP16(dst, src) asm volatile("cp.async.cg.shared.global [%0], [%1], 16;" :: "r"(dst), "l"(src) : "memory")
#define CP_COMMIT()    asm volatile("cp.async.commit_group;" ::: "memory")
#define CP_WAIT(n)     asm volatile("cp.async.wait_group %0;" :: "n"(n) : "memory")
#define LDSM_X4(r0, r1, r2, r3, a) \
    asm volatile("ldmatrix.sync.aligned.m8n8.x4.shared.b16 {%0,%1,%2,%3}, [%4];" \
        : "=r"(r0), "=r"(r1), "=r"(r2), "=r"(r3) : "r"(a))
#define MMA_F16(d0, d1, a0, a1, a2, a3, b0, b1) \
    asm volatile("mma.sync.aligned.m16n8k16.row.col.f16.f16.f16.f16 " \
        "{%0,%1},{%2,%3,%4,%5},{%6,%7},{%0,%1};" \
        : "+r"(d0), "+r"(d1) \
        : "r"(a0), "r"(a1), "r"(a2), "r"(a3), "r"(b0), "r"(b1))

// ---------------- Kernel A: norms + fp16 convert + counter reset ----------------
__global__ void sq_kernel(const float* __restrict__ feats) {
    int gw = (blockIdx.x * blockDim.x + threadIdx.x) >> 5;
    int lane = threadIdx.x & 31;
    if (gw >= NN) return;
    const float4* rowp = (const float4*)(feats + (size_t)gw * DD);
    float4 a = rowp[lane];
    float4 b = rowp[lane + 32];
    float s = a.x*a.x + a.y*a.y + a.z*a.z + a.w*a.w
            + b.x*b.x + b.y*b.y + b.z*b.z + b.w*b.w;
    #pragma unroll
    for (int o = 16; o; o >>= 1) s += __shfl_xor_sync(0xffffffffu, s, o);
    if (lane == 0) { g_sq[gw] = s; g_bcnt[gw] = 0; }
    __half2* dst = g_fh16 + (size_t)gw * (DD / 2);
    dst[lane * 2]          = __floats2half2_rn(a.x, a.y);
    dst[lane * 2 + 1]      = __floats2half2_rn(a.z, a.w);
    dst[64 + lane * 2]     = __floats2half2_rn(b.x, b.y);
    dst[64 + lane * 2 + 1] = __floats2half2_rn(b.z, b.w);
}

// dummy: occupies launch slot #3 so screen_kernel (launch #4) gets ncu-profiled
__global__ void dummy_kernel() {}

// ---------------- Kernel T: sample 512 cols -> per-row tau (20th-smallest key) ----------------
struct SmemT {
    __half A[BM][RSB];
    __half B[2][BN][RSB];
    float sqB[2][BN];
    float thr[BM];
    int   cnt[BM];
    unsigned long long best[BM][MST];
    unsigned long long cand[BM][BN];
};

__device__ __forceinline__ void prefetch_BT(SmemT& sm, int s, int j0, int tid) {
    #pragma unroll
    for (int t = 0; t < 8; ++t) {
        int idx = t * 256 + tid;
        int r = idx >> 5, ch = idx & 31;
        unsigned dst = smem_u32(&sm.B[s][r][ch * 8]);
        const void* src = (const char*)g_fh16 + (((size_t)(j0 + r) * DD) + ch * 8) * 2;
        CP16(dst, src);
    }
    if (tid < 16) {
        unsigned dst = smem_u32(&sm.sqB[s][tid * 4]);
        const void* src = g_sq + j0 + tid * 4;
        CP16(dst, src);
    }
}

__global__ void __launch_bounds__(256, 1) thresh_kernel() {
    extern __shared__ char raw[];
    SmemT& sm = *reinterpret_cast<SmemT*>(raw);
    const int tid = threadIdx.x;
    const int lane = tid & 31;
    const int w = tid >> 5;
    const int wr = w >> 1;
    const int wc = w & 1;
    const int i0 = blockIdx.x * BM;

    #pragma unroll
    for (int t = 0; t < 8; ++t) {
        int idx = t * 256 + tid;
        int r = idx >> 5, ch = idx & 31;
        unsigned dst = smem_u32(&sm.A[r][ch * 8]);
        const void* src = (const char*)g_fh16 + (((size_t)(i0 + r) * DD) + ch * 8) * 2;
        CP16(dst, src);
    }
    CP_COMMIT();
    prefetch_BT(sm, 0, 0, tid);
    CP_COMMIT();

    if (tid < BM) {
        sm.thr[tid] = __int_as_float(0x7f800000);
        sm.cnt[tid] = 0;
        #pragma unroll
        for (int t = 0; t < MST; ++t) sm.best[tid][t] = ULLINF;
    }

    const unsigned aAddr = smem_u32(&sm.A[wr * 16 + (lane & 15)][0]) + ((lane >> 4) << 4);
    const int rowB = wc * 32 + ((lane >> 4) << 3) + (lane & 7);
    const unsigned bColOff = ((lane >> 3) & 1) << 4;
    unsigned bAddrBase[2];
    bAddrBase[0] = smem_u32(&sm.B[0][rowB][0]) + bColOff;
    bAddrBase[1] = smem_u32(&sm.B[1][rowB][0]) + bColOff;

    const int R0 = wr * 16 + (lane >> 2);
    const int R1 = R0 + 8;
    const int cBase = wc * 32 + 2 * (lane & 3);

    for (int jt = 0; jt < JTS; ++jt) {
        const int s = jt & 1;
        const int j0 = jt * BN;

        if (jt + 1 < JTS) {
            prefetch_BT(sm, s ^ 1, (jt + 1) * BN, tid);
            CP_COMMIT();
            CP_WAIT(1);
        } else {
            CP_WAIT(0);
        }
        __syncthreads();

        unsigned acc[4][2];
        #pragma unroll
        for (int nt = 0; nt < 4; ++nt) { acc[nt][0] = 0u; acc[nt][1] = 0u; }

        const unsigned bA = bAddrBase[s];
        #pragma unroll
        for (int ks = 0; ks < 16; ++ks) {
            unsigned a0, a1, a2, a3;
            LDSM_X4(a0, a1, a2, a3, aAddr + ks * 32);
            unsigned p00, p01, p10, p11, q00, q01, q10, q11;
            LDSM_X4(p00, p01, p10, p11, bA + ks * 32);
            LDSM_X4(q00, q01, q10, q11, bA + 16 * (RSB * 2) + ks * 32);
            MMA_F16(acc[0][0], acc[0][1], a0, a1, a2, a3, p00, p01);
            MMA_F16(acc[1][0], acc[1][1], a0, a1, a2, a3, p10, p11);
            MMA_F16(acc[2][0], acc[2][1], a0, a1, a2, a3, q00, q01);
            MMA_F16(acc[3][0], acc[3][1], a0, a1, a2, a3, q10, q11);
        }

        const float t0 = sm.thr[R0];
        const float t1 = sm.thr[R1];
        const float* sq = sm.sqB[s];
        #pragma unroll
        for (int nt = 0; nt < 4; ++nt) {
            const int c = cBase + nt * 8;
            float2 f0 = __half22float2(*(__half2*)&acc[nt][0]);
            float2 f1 = __half22float2(*(__half2*)&acc[nt][1]);
            float v00 = fmaf(-2.f, f0.x, sq[c]);
            float v01 = fmaf(-2.f, f0.y, sq[c + 1]);
            float v10 = fmaf(-2.f, f1.x, sq[c]);
            float v11 = fmaf(-2.f, f1.y, sq[c + 1]);
            if (v00 < t0) { int p = atomicAdd(&sm.cnt[R0], 1);
                sm.cand[R0][p] = ((unsigned long long)mono(v00) << 32) | (unsigned)(j0 + c); }
            if (v01 < t0) { int p = atomicAdd(&sm.cnt[R0], 1);
                sm.cand[R0][p] = ((unsigned long long)mono(v01) << 32) | (unsigned)(j0 + c + 1); }
            if (v10 < t1) { int p = atomicAdd(&sm.cnt[R1], 1);
                sm.cand[R1][p] = ((unsigned long long)mono(v10) << 32) | (unsigned)(j0 + c); }
            if (v11 < t1) { int p = atomicAdd(&sm.cnt[R1], 1);
                sm.cand[R1][p] = ((unsigned long long)mono(v11) << 32) | (unsigned)(j0 + c + 1); }
        }
        __syncthreads();

        if (tid < BM) {
            int n = sm.cnt[tid];
            if (n) {
                sm.cnt[tid] = 0;
                unsigned long long* bl = sm.best[tid];
                for (int q = 0; q < n; ++q) {
                    unsigned long long key = sm.cand[tid][q];
                    if (key < bl[MST - 1]) {
                        int p = MST - 1;
                        while (p > 0 && bl[p - 1] > key) { bl[p] = bl[p - 1]; --p; }
                        bl[p] = key;
                    }
                }
                sm.thr[tid] = unmono((unsigned)(bl[MST - 1] >> 32));
            }
        }
    }

    if (tid < BM)
        g_tau[i0 + tid] = unmono((unsigned)(sm.best[tid][MST - 1] >> 32));
}

// ---------------- Kernel S: cyclic symmetric screen, split j-range, 2 CTAs/SM ----------------
struct SmemS {
    __half A[BM][RSB];                 // 33792
    __half B[BN][RSB];                 // 33792 (single buffer)
    float sqB[BN], tauB[BN];
    float sqA[BM], tauA[BM];
    float thr[BM];
    int   cnt[BM];
    unsigned long long best[BM][MS];   // 12288
    unsigned long long cand[BM][CCAP]; // 8192
    unsigned long long tval[TCAP];     // 4096
    unsigned char tcol[TCAP];
    int tcnt;
};

__global__ void __launch_bounds__(STH, 2) screen_kernel() {
    extern __shared__ char raw[];
    SmemS& sm = *reinterpret_cast<SmemS*>(raw);
    const int tid = threadIdx.x;
    const int lane = tid & 31;
    const int w = tid >> 5;            // 0..15
    const int wr = w >> 2;             // 0..3 -> 16-row strip
    const int wc = w & 3;              // 0..3 -> 16-col strip
    const int bx = blockIdx.x;
    const int it = bx >> 1;
    const int h  = bx & 1;
    const int i0 = it * BM;
    const int NT = (it < 64) ? 65 : 64;
    const int tb = h ? (NT + 1) / 2 : 0;
    const int te = h ? NT : (NT + 1) / 2;

    // A tile load (cp.async): 64 rows x 32 chunks = 2048 / 512 = 4 per thread
    #pragma unroll
    for (int t = 0; t < 4; ++t) {
        int idx = t * STH + tid;
        int r = idx >> 5, ch = idx & 31;
        unsigned dst = smem_u32(&sm.A[r][ch * 8]);
        const void* src = (const char*)g_fh16 + (((size_t)(i0 + r) * DD) + ch * 8) * 2;
        CP16(dst, src);
    }
    CP_COMMIT();

    if (tid < BM) {
        sm.sqA[tid]  = g_sq[i0 + tid];
        float tau = g_tau[i0 + tid];
        sm.tauA[tid] = tau;
        sm.thr[tid]  = tau;           // order-statistic bound: top-17 always passes
        sm.cnt[tid]  = 0;
        #pragma unroll
        for (int t = 0; t < MS; ++t) sm.best[tid][t] = ULLINF;
    }
    if (tid == 0) sm.tcnt = 0;

    const unsigned aAddr = smem_u32(&sm.A[wr * 16 + (lane & 15)][0]) + ((lane >> 4) << 4);
    const int rowB = wc * 16 + ((lane >> 4) << 3) + (lane & 7);
    const unsigned bColOff = ((lane >> 3) & 1) << 4;
    const unsigned bAddr = smem_u32(&sm.B[rowB][0]) + bColOff;

    const int R0 = wr * 16 + (lane >> 2);
    const int R1 = R0 + 8;
    const int cBase = wc * 16 + 2 * (lane & 3);

    for (int t = tb; t < te; ++t) {
        const int jt = (it + t) & (NTILE - 1);
        const int j0 = jt * BN;
        const bool offdiag = (t != 0);

        __syncthreads();   // prev drain/flush done; B free; init visible (first iter)
        if (tid == 0) sm.tcnt = 0;
        #pragma unroll
        for (int q = 0; q < 4; ++q) {
            int idx = q * STH + tid;
            int r = idx >> 5, ch = idx & 31;
            unsigned dst = smem_u32(&sm.B[r][ch * 8]);
            const void* src = (const char*)g_fh16 + (((size_t)(j0 + r) * DD) + ch * 8) * 2;
            CP16(dst, src);
        }
        if (tid < BN) {
            sm.sqB[tid]  = g_sq[j0 + tid];
            sm.tauB[tid] = g_tau[j0 + tid];
        }
        CP_COMMIT();
        CP_WAIT(0);
        __syncthreads();   // B + sq/tau visible to all

        unsigned acc[2][2];
        acc[0][0] = 0u; acc[0][1] = 0u; acc[1][0] = 0u; acc[1][1] = 0u;

        #pragma unroll
        for (int ks = 0; ks < 16; ++ks) {
            unsigned a0, a1, a2, a3;
            LDSM_X4(a0, a1, a2, a3, aAddr + ks * 32);
            unsigned p0, p1, p2, p3;
            LDSM_X4(p0, p1, p2, p3, bAddr + ks * 32);
            MMA_F16(acc[0][0], acc[0][1], a0, a1, a2, a3, p0, p1);
            MMA_F16(acc[1][0], acc[1][1], a0, a1, a2, a3, p2, p3);
        }

        // --- epilogue: 8 elements/thread, mask-coalesced ---
        const float t0 = sm.thr[R0];
        const float t1 = sm.thr[R1];
        const float sqa0 = sm.sqA[R0];
        const float sqa1 = sm.sqA[R1];
        const float* sq = sm.sqB;
        const float* tbv = sm.tauB;

        float sv[8];
        {
            float2 f0 = __half22float2(*(__half2*)&acc[0][0]);
            float2 f1 = __half22float2(*(__half2*)&acc[0][1]);
            float2 g0 = __half22float2(*(__half2*)&acc[1][0]);
            float2 g1 = __half22float2(*(__half2*)&acc[1][1]);
            sv[0] = f0.x; sv[1] = f0.y; sv[2] = f1.x; sv[3] = f1.y;
            sv[4] = g0.x; sv[5] = g0.y; sv[6] = g1.x; sv[7] = g1.y;
        }
        float vl[8], wt[8];
        unsigned mL = 0, mT = 0;
        #pragma unroll
        for (int e = 0; e < 8; ++e) {
            const int k = e & 3;
            const int col = cBase + (e >> 2) * 8 + (k & 1);
            const bool hi = (k >= 2);
            vl[e] = fmaf(-2.f, sv[e], sq[col]);
            wt[e] = fmaf(-2.f, sv[e], hi ? sqa1 : sqa0);
            if (vl[e] < (hi ? t1 : t0)) mL |= 1u << e;
            if (wt[e] <= tbv[col])      mT |= 1u << e;
        }
        if (!offdiag) mT = 0;
        if (mL) {
            #pragma unroll
            for (int e = 0; e < 8; ++e) if (mL & (1u << e)) {
                const int k = e & 3;
                const int row = (k >= 2) ? R1 : R0;
                const int col = cBase + (e >> 2) * 8 + (k & 1);
                unsigned long long key = ((unsigned long long)mono(vl[e]) << 32) | (unsigned)(j0 + col);
                int p = atomicAdd(&sm.cnt[row], 1);
                if (p < CCAP) sm.cand[row][p] = key;
                else { int g = atomicAdd(&g_bcnt[i0 + row], 1);
                       if (g < CAP) g_buf[(size_t)(i0 + row) * CAP + g] = key; }
            }
        }
        if (mT) {
            #pragma unroll
            for (int e = 0; e < 8; ++e) if (mT & (1u << e)) {
                const int k = e & 3;
                const int row = (k >= 2) ? R1 : R0;
                const int col = cBase + (e >> 2) * 8 + (k & 1);
                unsigned long long val = ((unsigned long long)mono(wt[e]) << 32) | (unsigned)(i0 + row);
                int p = atomicAdd(&sm.tcnt, 1);
                if (p < TCAP) { sm.tval[p] = val; sm.tcol[p] = (unsigned char)col; }
                else { int g = atomicAdd(&g_bcnt[j0 + col], 1);
                       if (g < CAP) g_buf[(size_t)(j0 + col) * CAP + g] = val; }
            }
        }
        __syncthreads();   // epilogue complete

        // cooperative drain of staged transpose appends
        {
            int n = sm.tcnt;
            if (n > TCAP) n = TCAP;
            for (int q = tid; q < n; q += STH) {
                int trow = j0 + (int)sm.tcol[q];
                int p = atomicAdd(&g_bcnt[trow], 1);
                if (p < CAP) g_buf[(size_t)trow * CAP + p] = sm.tval[q];
            }
        }
        // local flush (tid<BM) concurrent with the drain
        if (tid < BM) {
            int n = sm.cnt[tid];
            if (n) {
                if (n > CCAP) n = CCAP;
                sm.cnt[tid] = 0;
                unsigned long long* bl = sm.best[tid];
                for (int q = 0; q < n; ++q) {
                    unsigned long long key = sm.cand[tid][q];
                    if (key < bl[MS - 1]) {
                        int p = MS - 1;
                        while (p > 0 && bl[p - 1] > key) { bl[p] = bl[p - 1]; --p; }
                        bl[p] = key;
                    }
                }
                sm.thr[tid] = fminf(sm.tauA[tid], unmono((unsigned)(bl[MS - 1] >> 32)));
            }
        }
    }
    __syncthreads();

    for (int idx = tid; idx < BM * MS; idx += STH) {
        int r = idx / MS, q = idx % MS;
        g_loc[((size_t)(i0 + r) * 2 + h) * MS + q] = sm.best[r][q];
    }
}

// ---------------- Kernel L: warp-per-row merge of 2x local top-24 + buffer -> top-28 ----------------
__global__ void __launch_bounds__(256) sel_kernel() {
    __shared__ unsigned long long ch[8][32][15];
    const int lane = threadIdx.x & 31;
    const int w = threadIdx.x >> 5;
    const int row = blockIdx.x * 8 + w;

    unsigned long long* my = ch[w][lane];
    int len = 0;
    const unsigned long long* lp = g_loc + (size_t)row * 2 * MS;
    for (int q = lane; q < 2 * MS; q += 32) {
        unsigned long long key = lp[q];
        int p = len++;
        while (p > 0 && my[p - 1] > key) { my[p] = my[p - 1]; --p; }
        my[p] = key;
    }
    int cnt = g_bcnt[row];
    if (cnt > SCAP) cnt = SCAP;
    const unsigned long long* bp = g_buf + (size_t)row * CAP;
    for (int q = lane; q < cnt; q += 32) {
        unsigned long long key = bp[q];
        int p = len++;
        while (p > 0 && my[p - 1] > key) { my[p] = my[p - 1]; --p; }
        my[p] = key;
    }
    __syncwarp();

    int ptr = 0;
    for (int sel = 0; sel < RS28; ++sel) {
        unsigned long long hKey = (ptr < len) ? my[ptr] : ULLINF;
        unsigned long long M = hKey;
        #pragma unroll
        for (int o = 16; o; o >>= 1) {
            unsigned long long v = __shfl_xor_sync(0xffffffffu, M, o);
            M = (v < M) ? v : M;
        }
        unsigned b = __ballot_sync(0xffffffffu, hKey == M && M != ULLINF);
        if (b && lane == (__ffs(b) - 1)) ++ptr;
        if (lane == 0) g_cand[(size_t)row * RS28 + sel] = M;
    }
}

// ---------------- Kernel R: exact fp32 refine of 28 survivors -> exact top-17 ----------------
__global__ void refine_kernel(const float* __restrict__ feats) {
    int row = (blockIdx.x * blockDim.x + threadIdx.x) >> 5;
    int lane = threadIdx.x & 31;
    if (row >= NN) return;

    const float* base = feats + (size_t)row * DD;
    float4 a0 = *(const float4*)(base + lane * 4);
    float4 a1 = *(const float4*)(base + 128 + lane * 4);
    float own[8] = {a0.x, a0.y, a0.z, a0.w, a1.x, a1.y, a1.z, a1.w};

    unsigned long long mykey = ULLINF;

    #pragma unroll 4
    for (int t = 0; t < RS28; ++t) {
        unsigned long long ak = g_cand[(size_t)row * RS28 + t];
        int j = (ak == ULLINF) ? 0 : (int)(unsigned)(ak & 0xffffffffull);
        const float* nb = feats + (size_t)j * DD;
        float4 b0 = *(const float4*)(nb + lane * 4);
        float4 b1 = *(const float4*)(nb + 128 + lane * 4);
        float p = own[0]*b0.x + own[1]*b0.y + own[2]*b0.z + own[3]*b0.w
                + own[4]*b1.x + own[5]*b1.y + own[6]*b1.z + own[7]*b1.w;
        #pragma unroll
        for (int o = 16; o; o >>= 1) p += __shfl_xor_sync(0xffffffffu, p, o);
        float val = fmaf(-2.f, p, g_sq[j]);
        unsigned long long key = (ak == ULLINF) ? ULLINF
                               : (((unsigned long long)mono(val) << 32) | (unsigned)j);
        if (lane == t) mykey = key;
    }

    int rank = 0;
    #pragma unroll
    for (int s = 0; s < RS28; ++s) {
        unsigned long long ok = __shfl_sync(0xffffffffu, mykey, s);
        rank += (ok < mykey);
    }
    if (lane < RS28 && rank < KSEL && mykey != ULLINF)
        g_best[(size_t)row * KSEL + rank] = mykey;
}

// ---------------- Kernel C: mutual mask + sparse softmax + AV + residual + normalize ----------------
__global__ void fuse_kernel(const float* __restrict__ feats, float* __restrict__ out) {
    int gw = (blockIdx.x * blockDim.x + threadIdx.x) >> 5;
    int lane = threadIdx.x & 31;
    if (gw >= NN) return;
    const int row = gw;
    const float* base = feats + (size_t)row * DD;
    float4 a0 = *(const float4*)(base + lane * 4);
    float4 a1 = *(const float4*)(base + 128 + lane * 4);
    float own[8] = {a0.x, a0.y, a0.z, a0.w, a1.x, a1.y, a1.z, a1.w};

    int my_nbr = -1;
    int cnt = 0;
    #pragma unroll
    for (int t = 0; t < KSEL; ++t) {
        unsigned long long key = g_best[(size_t)row * KSEL + t];
        int j = (int)(unsigned)(key & 0xffffffffull);
        if (j != row && cnt < KK) {
            if (cnt == lane) my_nbr = j;
            cnt++;
        }
    }

    bool found = false;
    if (lane < KK && my_nbr >= 0) {
        #pragma unroll
        for (int t = 0; t < KSEL; ++t) {
            unsigned long long key = g_best[(size_t)my_nbr * KSEL + t];
            if ((int)(unsigned)(key & 0xffffffffull) == row) found = true;
        }
    }
    unsigned mmask = __ballot_sync(0xffffffffu, found) & 0xffffu;

    float m = 1.0f, Z = 1.0f;
    float acc[8];
    #pragma unroll
    for (int e = 0; e < 8; ++e) acc[e] = own[e];

    for (int l = 0; l < KK; ++l) {
        if (!((mmask >> l) & 1u)) continue;
        int j = __shfl_sync(0xffffffffu, my_nbr, l);
        const float* nb = feats + (size_t)j * DD;
        float4 b0 = *(const float4*)(nb + lane * 4);
        float4 b1 = *(const float4*)(nb + 128 + lane * 4);
        float v[8] = {b0.x, b0.y, b0.z, b0.w, b1.x, b1.y, b1.z, b1.w};
        float p = 0.f;
        #pragma unroll
        for (int e = 0; e < 8; ++e) p = fmaf(own[e], v[e], p);
        #pragma unroll
        for (int o = 16; o; o >>= 1) p += __shfl_xor_sync(0xffffffffu, p, o);
        if (p > m) {
            float f = expf(m - p);
            Z = Z * f + 1.0f;
            #pragma unroll
            for (int e = 0; e < 8; ++e) acc[e] = fmaf(acc[e], f, v[e]);
            m = p;
        } else {
            float wgt = expf(p - m);
            Z += wgt;
            #pragma unroll
            for (int e = 0; e < 8; ++e) acc[e] = fmaf(wgt, v[e], acc[e]);
        }
    }

    float invZ = 1.0f / Z;
    float fcm[8];
    float ss = 0.f;
    #pragma unroll
    for (int e = 0; e < 8; ++e) {
        fcm[e] = fmaf(acc[e], invZ, own[e]);
        ss = fmaf(fcm[e], fcm[e], ss);
    }
    #pragma unroll
    for (int o = 16; o; o >>= 1) ss += __shfl_xor_sync(0xffffffffu, ss, o);
    float inv = 1.0f / fmaxf(sqrtf(ss), 1e-12f);

    float* op = out + (size_t)row * DD;
    *(float4*)(op + lane * 4)       = make_float4(fcm[0]*inv, fcm[1]*inv, fcm[2]*inv, fcm[3]*inv);
    *(float4*)(op + 128 + lane * 4) = make_float4(fcm[4]*inv, fcm[5]*inv, fcm[6]*inv, fcm[7]*inv);
}

// ---------------- launch ----------------
extern "C" void kernel_launch(void* const* d_in, const int* in_sizes, int n_in,
                              void* d_out, int out_size) {
    const float* feats = (const float*)d_in[0];
    float* out = (float*)d_out;
    (void)in_sizes; (void)n_in; (void)out_size;

    cudaFuncSetAttribute(thresh_kernel, cudaFuncAttributeMaxDynamicSharedMemorySize,
                         (int)sizeof(SmemT));
    cudaFuncSetAttribute(screen_kernel, cudaFuncAttributeMaxDynamicSharedMemorySize,
                         (int)sizeof(SmemS));

    sq_kernel<<<NN / 8, 256>>>(feats);
    thresh_kernel<<<NN / BM, 256, sizeof(SmemT)>>>();
    dummy_kernel<<<1, 32>>>();
    screen_kernel<<<NTILE * 2, STH, sizeof(SmemS)>>>();
    sel_kernel<<<NN / 8, 256>>>();
    refine_kernel<<<NN / 8, 256>>>(feats);
    fuse_kernel<<<NN / 8, 256>>>(feats, out);
}

// round 16
// speedup vs baseline: 1.3942x; 1.0127x over previous
#include <cuda_runtime.h>
#include <cuda_fp16.h>
#include <math.h>

#define NN 8192
#define DD 256
#define KK 16
#define KSEL 17
#define RS28 28           // refine candidates per row
#define MS 24             // local streaming top-M per row (per half)
#define BM 64
#define BN 64
#define BMT 32            // thresh rows per CTA (half tile)
#define NTILE 128         // 8192/64
#define JTS 8             // thresh-pass sample tiles (512 cols)
#define MST 20            // thresh-pass top-M -> tau
#define RSB 264           // smem row stride in fp16 elements (528B)
#define CAP 1024
#define TCAP 512          // per-tile transpose staging capacity
#define CCAP 16           // per-row per-tile local candidate cap (overflow -> g_buf)
#define SCAP 384          // per-row buffer scan cap in sel
#define STH 512           // screen threads (16 warps), 2 CTAs/SM
#define ULLINF 0xFFFFFFFFFFFFFFFFull

__device__ float g_sq[NN];
__device__ float g_tau[NN];
__device__ __half2 g_fh16[NN * DD / 2];
__device__ int g_bcnt[NN];
__device__ unsigned long long g_buf[(size_t)NN * CAP];
__device__ unsigned long long g_loc[(size_t)NN * 2 * MS];
__device__ unsigned long long g_cand[NN * RS28];
__device__ unsigned long long g_best[NN * KSEL];

__device__ __forceinline__ unsigned smem_u32(const void* p) {
    unsigned a;
    asm("{ .reg .u64 t; cvta.to.shared.u64 t, %1; cvt.u32.u64 %0, t; }" : "=r"(a) : "l"(p));
    return a;
}
__device__ __forceinline__ unsigned mono(float f) {
    unsigned u = __float_as_uint(f);
    return (u & 0x80000000u) ? ~u : (u | 0x80000000u);
}
__device__ __forceinline__ float unmono(unsigned u) {
    return __uint_as_float((u & 0x80000000u) ? (u ^ 0x80000000u) : ~u);
}

#define CP16(dst, src) asm volatile("cp.async.cg.shared.global [%0], [%1], 16;" :: "r"(dst), "l"(src) : "memory")
#define CP_COMMIT()    asm volatile("cp.async.commit_group;" ::: "memory")
#define CP_WAIT(n)     asm volatile("cp.async.wait_group %0;" :: "n"(n) : "memory")
#define LDSM_X4(r0, r1, r2, r3, a) \
    asm volatile("ldmatrix.sync.aligned.m8n8.x4.shared.b16 {%0,%1,%2,%3}, [%4];" \
        : "=r"(r0), "=r"(r1), "=r"(r2), "=r"(r3) : "r"(a))
#define MMA_F16(d0, d1, a0, a1, a2, a3, b0, b1) \
    asm volatile("mma.sync.aligned.m16n8k16.row.col.f16.f16.f16.f16 " \
        "{%0,%1},{%2,%3,%4,%5},{%6,%7},{%0,%1};" \
        : "+r"(d0), "+r"(d1) \
        : "r"(a0), "r"(a1), "r"(a2), "r"(a3), "r"(b0), "r"(b1))

// ---------------- Kernel A: norms + fp16 convert + counter reset ----------------
__global__ void sq_kernel(const float* __restrict__ feats) {
    int gw = (blockIdx.x * blockDim.x + threadIdx.x) >> 5;
    int lane = threadIdx.x & 31;
    if (gw >= NN) return;
    const float4* rowp = (const float4*)(feats + (size_t)gw * DD);
    float4 a = rowp[lane];
    float4 b = rowp[lane + 32];
    float s = a.x*a.x + a.y*a.y + a.z*a.z + a.w*a.w
            + b.x*b.x + b.y*b.y + b.z*b.z + b.w*b.w;
    #pragma unroll
    for (int o = 16; o; o >>= 1) s += __shfl_xor_sync(0xffffffffu, s, o);
    if (lane == 0) { g_sq[gw] = s; g_bcnt[gw] = 0; }
    __half2* dst = g_fh16 + (size_t)gw * (DD / 2);
    dst[lane * 2]          = __floats2half2_rn(a.x, a.y);
    dst[lane * 2 + 1]      = __floats2half2_rn(a.z, a.w);
    dst[64 + lane * 2]     = __floats2half2_rn(b.x, b.y);
    dst[64 + lane * 2 + 1] = __floats2half2_rn(b.z, b.w);
}

// dummy: occupies launch slot #3 so screen_kernel (launch #4) gets ncu-profiled
__global__ void dummy_kernel() {}

// ---------------- Kernel T: sample 512 cols -> per-row tau (32-row half CTAs, 2/SM) ----------------
struct SmemT {
    __half A[BMT][RSB];                // 16896
    __half B[2][BN][RSB];              // 67584
    float sqB[2][BN];
    float thr[BMT];
    int   cnt[BMT];
    unsigned long long best[BMT][MST]; // 5120
    unsigned long long cand[BMT][BN];  // 16384
};

__device__ __forceinline__ void prefetch_BT(SmemT& sm, int s, int j0, int tid) {
    #pragma unroll
    for (int t = 0; t < 8; ++t) {
        int idx = t * 256 + tid;
        int r = idx >> 5, ch = idx & 31;
        unsigned dst = smem_u32(&sm.B[s][r][ch * 8]);
        const void* src = (const char*)g_fh16 + (((size_t)(j0 + r) * DD) + ch * 8) * 2;
        CP16(dst, src);
    }
    if (tid < 16) {
        unsigned dst = smem_u32(&sm.sqB[s][tid * 4]);
        const void* src = g_sq + j0 + tid * 4;
        CP16(dst, src);
    }
}

__global__ void __launch_bounds__(256, 2) thresh_kernel() {
    extern __shared__ char raw[];
    SmemT& sm = *reinterpret_cast<SmemT*>(raw);
    const int tid = threadIdx.x;
    const int lane = tid & 31;
    const int w = tid >> 5;            // 0..7
    const int wr = w >> 2;             // 0..1 -> 16-row strip
    const int wc = w & 3;              // 0..3 -> 16-col strip
    const int i0 = (blockIdx.x >> 1) * BM + (blockIdx.x & 1) * BMT;

    // A tile: 32 rows x 32 chunks = 1024 / 256 = 4 per thread
    #pragma unroll
    for (int t = 0; t < 4; ++t) {
        int idx = t * 256 + tid;
        int r = idx >> 5, ch = idx & 31;
        unsigned dst = smem_u32(&sm.A[r][ch * 8]);
        const void* src = (const char*)g_fh16 + (((size_t)(i0 + r) * DD) + ch * 8) * 2;
        CP16(dst, src);
    }
    CP_COMMIT();
    prefetch_BT(sm, 0, 0, tid);
    CP_COMMIT();

    if (tid < BMT) {
        sm.thr[tid] = __int_as_float(0x7f800000);
        sm.cnt[tid] = 0;
        #pragma unroll
        for (int t = 0; t < MST; ++t) sm.best[tid][t] = ULLINF;
    }

    const unsigned aAddr = smem_u32(&sm.A[wr * 16 + (lane & 15)][0]) + ((lane >> 4) << 4);
    const int rowB = wc * 16 + ((lane >> 4) << 3) + (lane & 7);
    const unsigned bColOff = ((lane >> 3) & 1) << 4;
    unsigned bAddrBase[2];
    bAddrBase[0] = smem_u32(&sm.B[0][rowB][0]) + bColOff;
    bAddrBase[1] = smem_u32(&sm.B[1][rowB][0]) + bColOff;

    const int R0 = wr * 16 + (lane >> 2);
    const int R1 = R0 + 8;
    const int cBase = wc * 16 + 2 * (lane & 3);

    for (int jt = 0; jt < JTS; ++jt) {
        const int s = jt & 1;
        const int j0 = jt * BN;

        if (jt + 1 < JTS) {
            prefetch_BT(sm, s ^ 1, (jt + 1) * BN, tid);
            CP_COMMIT();
            CP_WAIT(1);
        } else {
            CP_WAIT(0);
        }
        __syncthreads();

        unsigned acc[2][2];
        acc[0][0] = 0u; acc[0][1] = 0u; acc[1][0] = 0u; acc[1][1] = 0u;

        const unsigned bA = bAddrBase[s];
        #pragma unroll
        for (int ks = 0; ks < 16; ++ks) {
            unsigned a0, a1, a2, a3;
            LDSM_X4(a0, a1, a2, a3, aAddr + ks * 32);
            unsigned p0, p1, p2, p3;
            LDSM_X4(p0, p1, p2, p3, bA + ks * 32);
            MMA_F16(acc[0][0], acc[0][1], a0, a1, a2, a3, p0, p1);
            MMA_F16(acc[1][0], acc[1][1], a0, a1, a2, a3, p2, p3);
        }

        const float t0 = sm.thr[R0];
        const float t1 = sm.thr[R1];
        const float* sq = sm.sqB[s];
        #pragma unroll
        for (int nt = 0; nt < 2; ++nt) {
            const int c = cBase + nt * 8;
            float2 f0 = __half22float2(*(__half2*)&acc[nt][0]);
            float2 f1 = __half22float2(*(__half2*)&acc[nt][1]);
            float v00 = fmaf(-2.f, f0.x, sq[c]);
            float v01 = fmaf(-2.f, f0.y, sq[c + 1]);
            float v10 = fmaf(-2.f, f1.x, sq[c]);
            float v11 = fmaf(-2.f, f1.y, sq[c + 1]);
            if (v00 < t0) { int p = atomicAdd(&sm.cnt[R0], 1);
                sm.cand[R0][p] = ((unsigned long long)mono(v00) << 32) | (unsigned)(j0 + c); }
            if (v01 < t0) { int p = atomicAdd(&sm.cnt[R0], 1);
                sm.cand[R0][p] = ((unsigned long long)mono(v01) << 32) | (unsigned)(j0 + c + 1); }
            if (v10 < t1) { int p = atomicAdd(&sm.cnt[R1], 1);
                sm.cand[R1][p] = ((unsigned long long)mono(v10) << 32) | (unsigned)(j0 + c); }
            if (v11 < t1) { int p = atomicAdd(&sm.cnt[R1], 1);
                sm.cand[R1][p] = ((unsigned long long)mono(v11) << 32) | (unsigned)(j0 + c + 1); }
        }
        __syncthreads();

        if (tid < BMT) {
            int n = sm.cnt[tid];
            if (n) {
                sm.cnt[tid] = 0;
                unsigned long long* bl = sm.best[tid];
                for (int q = 0; q < n; ++q) {
                    unsigned long long key = sm.cand[tid][q];
                    if (key < bl[MST - 1]) {
                        int p = MST - 1;
                        while (p > 0 && bl[p - 1] > key) { bl[p] = bl[p - 1]; --p; }
                        bl[p] = key;
                    }
                }
                sm.thr[tid] = unmono((unsigned)(bl[MST - 1] >> 32));
            }
        }
    }

    if (tid < BMT)
        g_tau[i0 + tid] = unmono((unsigned)(sm.best[tid][MST - 1] >> 32));
}

// ---------------- Kernel S: cyclic symmetric screen, prefetch-overlapped, 2 CTAs/SM ----------------
struct SmemS {
    __half A[BM][RSB];                 // 33792
    __half B[BN][RSB];                 // 33792 (single data buffer)
    float sqB[2][BN], tauB[2][BN];     // double-buffered scalars
    float sqA[BM], tauA[BM];
    float thr[BM];
    int   cnt[BM];
    unsigned long long best[BM][MS];   // 12288
    unsigned long long cand[BM][CCAP]; // 8192
    unsigned long long tval[2][TCAP];  // 8192
    unsigned char tcol[2][TCAP];       // 1024
    int tcnt[2];
};

__device__ __forceinline__ void load_BS(SmemS& sm, int sb, int j0, int tid) {
    #pragma unroll
    for (int q = 0; q < 4; ++q) {
        int idx = q * STH + tid;
        int r = idx >> 5, ch = idx & 31;
        unsigned dst = smem_u32(&sm.B[r][ch * 8]);
        const void* src = (const char*)g_fh16 + (((size_t)(j0 + r) * DD) + ch * 8) * 2;
        CP16(dst, src);
    }
    if (tid < 16) {
        unsigned dst = smem_u32(&sm.sqB[sb][tid * 4]);
        CP16(dst, (const void*)(g_sq + j0 + tid * 4));
    } else if (tid < 32) {
        int t = tid - 16;
        unsigned dst = smem_u32(&sm.tauB[sb][t * 4]);
        CP16(dst, (const void*)(g_tau + j0 + t * 4));
    }
}

__global__ void __launch_bounds__(STH, 2) screen_kernel() {
    extern __shared__ char raw[];
    SmemS& sm = *reinterpret_cast<SmemS*>(raw);
    const int tid = threadIdx.x;
    const int lane = tid & 31;
    const int w = tid >> 5;            // 0..15
    const int wr = w >> 2;             // 0..3 -> 16-row strip
    const int wc = w & 3;              // 0..3 -> 16-col strip
    const int bx = blockIdx.x;
    const int it = bx >> 1;
    const int h  = bx & 1;
    const int i0 = it * BM;
    const int NT = (it < 64) ? 65 : 64;
    const int tb = h ? (NT + 1) / 2 : 0;
    const int te = h ? NT : (NT + 1) / 2;

    // A tile
    #pragma unroll
    for (int t = 0; t < 4; ++t) {
        int idx = t * STH + tid;
        int r = idx >> 5, ch = idx & 31;
        unsigned dst = smem_u32(&sm.A[r][ch * 8]);
        const void* src = (const char*)g_fh16 + (((size_t)(i0 + r) * DD) + ch * 8) * 2;
        CP16(dst, src);
    }
    // first B tile + its scalars into parity (tb&1)
    load_BS(sm, tb & 1, ((it + tb) & (NTILE - 1)) * BN, tid);
    CP_COMMIT();

    if (tid < BM) {
        sm.sqA[tid]  = g_sq[i0 + tid];
        float tau = g_tau[i0 + tid];
        sm.tauA[tid] = tau;
        sm.thr[tid]  = tau;
        sm.cnt[tid]  = 0;
        #pragma unroll
        for (int t = 0; t < MS; ++t) sm.best[tid][t] = ULLINF;
    }
    if (tid == 0) { sm.tcnt[0] = 0; sm.tcnt[1] = 0; }
    CP_WAIT(0);
    __syncthreads();

    const unsigned aAddr = smem_u32(&sm.A[wr * 16 + (lane & 15)][0]) + ((lane >> 4) << 4);
    const int rowB = wc * 16 + ((lane >> 4) << 3) + (lane & 7);
    const unsigned bColOff = ((lane >> 3) & 1) << 4;
    const unsigned bAddr = smem_u32(&sm.B[rowB][0]) + bColOff;

    const int R0 = wr * 16 + (lane >> 2);
    const int R1 = R0 + 8;
    const int cBase = wc * 16 + 2 * (lane & 3);

    for (int t = tb; t < te; ++t) {
        const int s = t & 1;
        const int jt = (it + t) & (NTILE - 1);
        const int j0 = jt * BN;
        const bool offdiag = (t != 0);

        // ---- MMA over current B ----
        unsigned acc[2][2];
        acc[0][0] = 0u; acc[0][1] = 0u; acc[1][0] = 0u; acc[1][1] = 0u;
        #pragma unroll
        for (int ks = 0; ks < 16; ++ks) {
            unsigned a0, a1, a2, a3;
            LDSM_X4(a0, a1, a2, a3, aAddr + ks * 32);
            unsigned p0, p1, p2, p3;
            LDSM_X4(p0, p1, p2, p3, bAddr + ks * 32);
            MMA_F16(acc[0][0], acc[0][1], a0, a1, a2, a3, p0, p1);
            MMA_F16(acc[1][0], acc[1][1], a0, a1, a2, a3, p2, p3);
        }
        __syncthreads();   // all B reads done -> safe to overwrite B

        // ---- prefetch next tile (overlaps epilogue + drain/flush) ----
        if (t + 1 < te) {
            load_BS(sm, s ^ 1, ((it + t + 1) & (NTILE - 1)) * BN, tid);
            CP_COMMIT();
        }

        // ---- epilogue: 8 elements/thread, mask-coalesced ----
        const float t0 = sm.thr[R0];
        const float t1 = sm.thr[R1];
        const float sqa0 = sm.sqA[R0];
        const float sqa1 = sm.sqA[R1];
        const float* sq = sm.sqB[s];
        const float* tbv = sm.tauB[s];

        float sv[8];
        {
            float2 f0 = __half22float2(*(__half2*)&acc[0][0]);
            float2 f1 = __half22float2(*(__half2*)&acc[0][1]);
            float2 g0 = __half22float2(*(__half2*)&acc[1][0]);
            float2 g1 = __half22float2(*(__half2*)&acc[1][1]);
            sv[0] = f0.x; sv[1] = f0.y; sv[2] = f1.x; sv[3] = f1.y;
            sv[4] = g0.x; sv[5] = g0.y; sv[6] = g1.x; sv[7] = g1.y;
        }
        float vl[8], wt[8];
        unsigned mL = 0, mT = 0;
        #pragma unroll
        for (int e = 0; e < 8; ++e) {
            const int k = e & 3;
            const int col = cBase + (e >> 2) * 8 + (k & 1);
            const bool hi = (k >= 2);
            vl[e] = fmaf(-2.f, sv[e], sq[col]);
            wt[e] = fmaf(-2.f, sv[e], hi ? sqa1 : sqa0);
            if (vl[e] < (hi ? t1 : t0)) mL |= 1u << e;
            if (wt[e] <= tbv[col])      mT |= 1u << e;
        }
        if (!offdiag) mT = 0;
        if (mL) {
            #pragma unroll
            for (int e = 0; e < 8; ++e) if (mL & (1u << e)) {
                const int k = e & 3;
                const int row = (k >= 2) ? R1 : R0;
                const int col = cBase + (e >> 2) * 8 + (k & 1);
                unsigned long long key = ((unsigned long long)mono(vl[e]) << 32) | (unsigned)(j0 + col);
                int p = atomicAdd(&sm.cnt[row], 1);
                if (p < CCAP) sm.cand[row][p] = key;
                else { int g = atomicAdd(&g_bcnt[i0 + row], 1);
                       if (g < CAP) g_buf[(size_t)(i0 + row) * CAP + g] = key; }
            }
        }
        if (mT) {
            #pragma unroll
            for (int e = 0; e < 8; ++e) if (mT & (1u << e)) {
                const int k = e & 3;
                const int row = (k >= 2) ? R1 : R0;
                const int col = cBase + (e >> 2) * 8 + (k & 1);
                unsigned long long val = ((unsigned long long)mono(wt[e]) << 32) | (unsigned)(i0 + row);
                int p = atomicAdd(&sm.tcnt[s], 1);
                if (p < TCAP) { sm.tval[s][p] = val; sm.tcol[s][p] = (unsigned char)col; }
                else { int g = atomicAdd(&g_bcnt[j0 + col], 1);
                       if (g < CAP) g_buf[(size_t)(j0 + col) * CAP + g] = val; }
            }
        }
        __syncthreads();   // epilogue complete (cand/cnt, tval[s]/tcnt[s] stable)

        // ---- drain staged transpose appends + local flush (overlaps prefetch DMA) ----
        {
            int n = sm.tcnt[s];
            if (n > TCAP) n = TCAP;
            for (int q = tid; q < n; q += STH) {
                int trow = j0 + (int)sm.tcol[s][q];
                int p = atomicAdd(&g_bcnt[trow], 1);
                if (p < CAP) g_buf[(size_t)trow * CAP + p] = sm.tval[s][q];
            }
        }
        if (tid == 0) sm.tcnt[s ^ 1] = 0;    // reset next parity (read only after next epilogue)
        if (tid < BM) {
            int n = sm.cnt[tid];
            if (n) {
                if (n > CCAP) n = CCAP;
                sm.cnt[tid] = 0;
                unsigned long long* bl = sm.best[tid];
                for (int q = 0; q < n; ++q) {
                    unsigned long long key = sm.cand[tid][q];
                    if (key < bl[MS - 1]) {
                        int p = MS - 1;
                        while (p > 0 && bl[p - 1] > key) { bl[p] = bl[p - 1]; --p; }
                        bl[p] = key;
                    }
                }
                sm.thr[tid] = fminf(sm.tauA[tid], unmono((unsigned)(bl[MS - 1] >> 32)));
            }
        }
        CP_WAIT(0);        // next B tile landed
        __syncthreads();   // B + scalars + flush visible
    }

    for (int idx = tid; idx < BM * MS; idx += STH) {
        int r = idx / MS, q = idx % MS;
        g_loc[((size_t)(i0 + r) * 2 + h) * MS + q] = sm.best[r][q];
    }
}

// ---------------- Kernel L: warp-per-row merge of 2x local top-24 + buffer -> top-28 ----------------
__global__ void __launch_bounds__(256) sel_kernel() {
    __shared__ unsigned long long ch[8][32][15];
    const int lane = threadIdx.x & 31;
    const int w = threadIdx.x >> 5;
    const int row = blockIdx.x * 8 + w;

    unsigned long long* my = ch[w][lane];
    int len = 0;
    const unsigned long long* lp = g_loc + (size_t)row * 2 * MS;
    for (int q = lane; q < 2 * MS; q += 32) {
        unsigned long long key = lp[q];
        int p = len++;
        while (p > 0 && my[p - 1] > key) { my[p] = my[p - 1]; --p; }
        my[p] = key;
    }
    int cnt = g_bcnt[row];
    if (cnt > SCAP) cnt = SCAP;
    const unsigned long long* bp = g_buf + (size_t)row * CAP;
    for (int q = lane; q < cnt; q += 32) {
        unsigned long long key = bp[q];
        int p = len++;
        while (p > 0 && my[p - 1] > key) { my[p] = my[p - 1]; --p; }
        my[p] = key;
    }
    __syncwarp();

    int ptr = 0;
    for (int sel = 0; sel < RS28; ++sel) {
        unsigned long long hKey = (ptr < len) ? my[ptr] : ULLINF;
        unsigned long long M = hKey;
        #pragma unroll
        for (int o = 16; o; o >>= 1) {
            unsigned long long v = __shfl_xor_sync(0xffffffffu, M, o);
            M = (v < M) ? v : M;
        }
        unsigned b = __ballot_sync(0xffffffffu, hKey == M && M != ULLINF);
        if (b && lane == (__ffs(b) - 1)) ++ptr;
        if (lane == 0) g_cand[(size_t)row * RS28 + sel] = M;
    }
}

// ---------------- Kernel R: exact fp32 refine of 28 survivors -> exact top-17 ----------------
__global__ void refine_kernel(const float* __restrict__ feats) {
    int row = (blockIdx.x * blockDim.x + threadIdx.x) >> 5;
    int lane = threadIdx.x & 31;
    if (row >= NN) return;

    const float* base = feats + (size_t)row * DD;
    float4 a0 = *(const float4*)(base + lane * 4);
    float4 a1 = *(const float4*)(base + 128 + lane * 4);
    float own[8] = {a0.x, a0.y, a0.z, a0.w, a1.x, a1.y, a1.z, a1.w};

    unsigned long long mykey = ULLINF;

    #pragma unroll 4
    for (int t = 0; t < RS28; ++t) {
        unsigned long long ak = g_cand[(size_t)row * RS28 + t];
        int j = (ak == ULLINF) ? 0 : (int)(unsigned)(ak & 0xffffffffull);
        const float* nb = feats + (size_t)j * DD;
        float4 b0 = *(const float4*)(nb + lane * 4);
        float4 b1 = *(const float4*)(nb + 128 + lane * 4);
        float p = own[0]*b0.x + own[1]*b0.y + own[2]*b0.z + own[3]*b0.w
                + own[4]*b1.x + own[5]*b1.y + own[6]*b1.z + own[7]*b1.w;
        #pragma unroll
        for (int o = 16; o; o >>= 1) p += __shfl_xor_sync(0xffffffffu, p, o);
        float val = fmaf(-2.f, p, g_sq[j]);
        unsigned long long key = (ak == ULLINF) ? ULLINF
                               : (((unsigned long long)mono(val) << 32) | (unsigned)j);
        if (lane == t) mykey = key;
    }

    int rank = 0;
    #pragma unroll
    for (int s = 0; s < RS28; ++s) {
        unsigned long long ok = __shfl_sync(0xffffffffu, mykey, s);
        rank += (ok < mykey);
    }
    if (lane < RS28 && rank < KSEL && mykey != ULLINF)
        g_best[(size_t)row * KSEL + rank] = mykey;
}

// ---------------- Kernel C: mutual mask + sparse softmax + AV + residual + normalize ----------------
__global__ void fuse_kernel(const float* __restrict__ feats, float* __restrict__ out) {
    int gw = (blockIdx.x * blockDim.x + threadIdx.x) >> 5;
    int lane = threadIdx.x & 31;
    if (gw >= NN) return;
    const int row = gw;
    const float* base = feats + (size_t)row * DD;
    float4 a0 = *(const float4*)(base + lane * 4);
    float4 a1 = *(const float4*)(base + 128 + lane * 4);
    float own[8] = {a0.x, a0.y, a0.z, a0.w, a1.x, a1.y, a1.z, a1.w};

    int my_nbr = -1;
    int cnt = 0;
    #pragma unroll
    for (int t = 0; t < KSEL; ++t) {
        unsigned long long key = g_best[(size_t)row * KSEL + t];
        int j = (int)(unsigned)(key & 0xffffffffull);
        if (j != row && cnt < KK) {
            if (cnt == lane) my_nbr = j;
            cnt++;
        }
    }

    bool found = false;
    if (lane < KK && my_nbr >= 0) {
        #pragma unroll
        for (int t = 0; t < KSEL; ++t) {
            unsigned long long key = g_best[(size_t)my_nbr * KSEL + t];
            if ((int)(unsigned)(key & 0xffffffffull) == row) found = true;
        }
    }
    unsigned mmask = __ballot_sync(0xffffffffu, found) & 0xffffu;

    float m = 1.0f, Z = 1.0f;
    float acc[8];
    #pragma unroll
    for (int e = 0; e < 8; ++e) acc[e] = own[e];

    for (int l = 0; l < KK; ++l) {
        if (!((mmask >> l) & 1u)) continue;
        int j = __shfl_sync(0xffffffffu, my_nbr, l);
        const float* nb = feats + (size_t)j * DD;
        float4 b0 = *(const float4*)(nb + lane * 4);
        float4 b1 = *(const float4*)(nb + 128 + lane * 4);
        float v[8] = {b0.x, b0.y, b0.z, b0.w, b1.x, b1.y, b1.z, b1.w};
        float p = 0.f;
        #pragma unroll
        for (int e = 0; e < 8; ++e) p = fmaf(own[e], v[e], p);
        #pragma unroll
        for (int o = 16; o; o >>= 1) p += __shfl_xor_sync(0xffffffffu, p, o);
        if (p > m) {
            float f = expf(m - p);
            Z = Z * f + 1.0f;
            #pragma unroll
            for (int e = 0; e < 8; ++e) acc[e] = fmaf(acc[e], f, v[e]);
            m = p;
        } else {
            float wgt = expf(p - m);
            Z += wgt;
            #pragma unroll
            for (int e = 0; e < 8; ++e) acc[e] = fmaf(wgt, v[e], acc[e]);
        }
    }

    float invZ = 1.0f / Z;
    float fcm[8];
    float ss = 0.f;
    #pragma unroll
    for (int e = 0; e < 8; ++e) {
        fcm[e] = fmaf(acc[e], invZ, own[e]);
        ss = fmaf(fcm[e], fcm[e], ss);
    }
    #pragma unroll
    for (int o = 16; o; o >>= 1) ss += __shfl_xor_sync(0xffffffffu, ss, o);
    float inv = 1.0f / fmaxf(sqrtf(ss), 1e-12f);

    float* op = out + (size_t)row * DD;
    *(float4*)(op + lane * 4)       = make_float4(fcm[0]*inv, fcm[1]*inv, fcm[2]*inv, fcm[3]*inv);
    *(float4*)(op + 128 + lane * 4) = make_float4(fcm[4]*inv, fcm[5]*inv, fcm[6]*inv, fcm[7]*inv);
}

// ---------------- launch ----------------
extern "C" void kernel_launch(void* const* d_in, const int* in_sizes, int n_in,
                              void* d_out, int out_size) {
    const float* feats = (const float*)d_in[0];
    float* out = (float*)d_out;
    (void)in_sizes; (void)n_in; (void)out_size;

    cudaFuncSetAttribute(thresh_kernel, cudaFuncAttributeMaxDynamicSharedMemorySize,
                         (int)sizeof(SmemT));
    cudaFuncSetAttribute(screen_kernel, cudaFuncAttributeMaxDynamicSharedMemorySize,
                         (int)sizeof(SmemS));

    sq_kernel<<<NN / 8, 256>>>(feats);
    thresh_kernel<<<NTILE * 2, 256, sizeof(SmemT)>>>();
    dummy_kernel<<<1, 32>>>();
    screen_kernel<<<NTILE * 2, STH, sizeof(SmemS)>>>();
    sel_kernel<<<NN / 8, 256>>>();
    refine_kernel<<<NN / 8, 256>>>(feats);
    fuse_kernel<<<NN / 8, 256>>>(feats, out);
}

// round 17
// speedup vs baseline: 1.4089x; 1.0106x over previous
#include <cuda_runtime.h>
#include <cuda_fp16.h>
#include <math.h>

#define NN 8192
#define DD 256
#define KK 16
#define KSEL 17
#define RS28 28           // refine candidates per row
#define MS 24             // local streaming top-M per row (per half)
#define BM 64
#define BN 64
#define BMT 32            // thresh rows per CTA (half tile)
#define NTILE 128         // 8192/64
#define JTS 8             // thresh-pass sample tiles (512 cols)
#define MST 20            // thresh-pass top-M -> tau
#define RSB 264           // smem row stride in fp16 elements (528B)
#define CAP 1024
#define TCAP 512          // per-tile transpose staging capacity
#define CCAP 16           // per-row per-tile local candidate cap (overflow -> g_buf)
#define SCAP 384          // per-row buffer scan cap in selref
#define STH 512           // screen threads (16 warps), 2 CTAs/SM
#define ULLINF 0xFFFFFFFFFFFFFFFFull

__device__ float g_sq[NN];
__device__ float g_tau[NN];
__device__ __half2 g_fh16[NN * DD / 2];
__device__ int g_bcnt[NN];
__device__ unsigned long long g_buf[(size_t)NN * CAP];
__device__ unsigned long long g_loc[(size_t)NN * 2 * MS];
__device__ unsigned long long g_best[NN * KSEL];

__device__ __forceinline__ unsigned smem_u32(const void* p) {
    unsigned a;
    asm("{ .reg .u64 t; cvta.to.shared.u64 t, %1; cvt.u32.u64 %0, t; }" : "=r"(a) : "l"(p));
    return a;
}
__device__ __forceinline__ unsigned mono(float f) {
    unsigned u = __float_as_uint(f);
    return (u & 0x80000000u) ? ~u : (u | 0x80000000u);
}
__device__ __forceinline__ float unmono(unsigned u) {
    return __uint_as_float((u & 0x80000000u) ? (u ^ 0x80000000u) : ~u);
}

#define CP16(dst, src) asm volatile("cp.async.cg.shared.global [%0], [%1], 16;" :: "r"(dst), "l"(src) : "memory")
#define CP_COMMIT()    asm volatile("cp.async.commit_group;" ::: "memory")
#define CP_WAIT(n)     asm volatile("cp.async.wait_group %0;" :: "n"(n) : "memory")
#define LDSM_X4(r0, r1, r2, r3, a) \
    asm volatile("ldmatrix.sync.aligned.m8n8.x4.shared.b16 {%0,%1,%2,%3}, [%4];" \
        : "=r"(r0), "=r"(r1), "=r"(r2), "=r"(r3) : "r"(a))
#define MMA_F16(d0, d1, a0, a1, a2, a3, b0, b1) \
    asm volatile("mma.sync.aligned.m16n8k16.row.col.f16.f16.f16.f16 " \
        "{%0,%1},{%2,%3,%4,%5},{%6,%7},{%0,%1};" \
        : "+r"(d0), "+r"(d1) \
        : "r"(a0), "r"(a1), "r"(a2), "r"(a3), "r"(b0), "r"(b1))

// ---------------- Kernel A: norms + fp16 convert + counter reset ----------------
__global__ void sq_kernel(const float* __restrict__ feats) {
    int gw = (blockIdx.x * blockDim.x + threadIdx.x) >> 5;
    int lane = threadIdx.x & 31;
    if (gw >= NN) return;
    const float4* rowp = (const float4*)(feats + (size_t)gw * DD);
    float4 a = rowp[lane];
    float4 b = rowp[lane + 32];
    float s = a.x*a.x + a.y*a.y + a.z*a.z + a.w*a.w
            + b.x*b.x + b.y*b.y + b.z*b.z + b.w*b.w;
    #pragma unroll
    for (int o = 16; o; o >>= 1) s += __shfl_xor_sync(0xffffffffu, s, o);
    if (lane == 0) { g_sq[gw] = s; g_bcnt[gw] = 0; }
    __half2* dst = g_fh16 + (size_t)gw * (DD / 2);
    dst[lane * 2]          = __floats2half2_rn(a.x, a.y);
    dst[lane * 2 + 1]      = __floats2half2_rn(a.z, a.w);
    dst[64 + lane * 2]     = __floats2half2_rn(b.x, b.y);
    dst[64 + lane * 2 + 1] = __floats2half2_rn(b.z, b.w);
}

// dummy: occupies launch slot #3 so screen_kernel (launch #4) gets ncu-profiled
__global__ void dummy_kernel() {}

// ---------------- Kernel T: sample 512 cols -> per-row tau (32-row half CTAs, 2/SM) ----------------
struct SmemT {
    __half A[BMT][RSB];
    __half B[2][BN][RSB];
    float sqB[2][BN];
    float thr[BMT];
    int   cnt[BMT];
    unsigned long long best[BMT][MST];
    unsigned long long cand[BMT][BN];
};

__device__ __forceinline__ void prefetch_BT(SmemT& sm, int s, int j0, int tid) {
    #pragma unroll
    for (int t = 0; t < 8; ++t) {
        int idx = t * 256 + tid;
        int r = idx >> 5, ch = idx & 31;
        unsigned dst = smem_u32(&sm.B[s][r][ch * 8]);
        const void* src = (const char*)g_fh16 + (((size_t)(j0 + r) * DD) + ch * 8) * 2;
        CP16(dst, src);
    }
    if (tid < 16) {
        unsigned dst = smem_u32(&sm.sqB[s][tid * 4]);
        const void* src = g_sq + j0 + tid * 4;
        CP16(dst, src);
    }
}

__global__ void __launch_bounds__(256, 2) thresh_kernel() {
    extern __shared__ char raw[];
    SmemT& sm = *reinterpret_cast<SmemT*>(raw);
    const int tid = threadIdx.x;
    const int lane = tid & 31;
    const int w = tid >> 5;
    const int wr = w >> 2;
    const int wc = w & 3;
    const int i0 = (blockIdx.x >> 1) * BM + (blockIdx.x & 1) * BMT;

    #pragma unroll
    for (int t = 0; t < 4; ++t) {
        int idx = t * 256 + tid;
        int r = idx >> 5, ch = idx & 31;
        unsigned dst = smem_u32(&sm.A[r][ch * 8]);
        const void* src = (const char*)g_fh16 + (((size_t)(i0 + r) * DD) + ch * 8) * 2;
        CP16(dst, src);
    }
    CP_COMMIT();
    prefetch_BT(sm, 0, 0, tid);
    CP_COMMIT();

    if (tid < BMT) {
        sm.thr[tid] = __int_as_float(0x7f800000);
        sm.cnt[tid] = 0;
        #pragma unroll
        for (int t = 0; t < MST; ++t) sm.best[tid][t] = ULLINF;
    }

    const unsigned aAddr = smem_u32(&sm.A[wr * 16 + (lane & 15)][0]) + ((lane >> 4) << 4);
    const int rowB = wc * 16 + ((lane >> 4) << 3) + (lane & 7);
    const unsigned bColOff = ((lane >> 3) & 1) << 4;
    unsigned bAddrBase[2];
    bAddrBase[0] = smem_u32(&sm.B[0][rowB][0]) + bColOff;
    bAddrBase[1] = smem_u32(&sm.B[1][rowB][0]) + bColOff;

    const int R0 = wr * 16 + (lane >> 2);
    const int R1 = R0 + 8;
    const int cBase = wc * 16 + 2 * (lane & 3);

    for (int jt = 0; jt < JTS; ++jt) {
        const int s = jt & 1;
        const int j0 = jt * BN;

        if (jt + 1 < JTS) {
            prefetch_BT(sm, s ^ 1, (jt + 1) * BN, tid);
            CP_COMMIT();
            CP_WAIT(1);
        } else {
            CP_WAIT(0);
        }
        __syncthreads();

        unsigned acc[2][2];
        acc[0][0] = 0u; acc[0][1] = 0u; acc[1][0] = 0u; acc[1][1] = 0u;

        const unsigned bA = bAddrBase[s];
        // fragment double-buffered k-loop
        unsigned a0, a1, a2, a3, p0, p1, p2, p3;
        LDSM_X4(a0, a1, a2, a3, aAddr);
        LDSM_X4(p0, p1, p2, p3, bA);
        #pragma unroll
        for (int ks = 0; ks < 16; ++ks) {
            unsigned na0, na1, na2, na3, np0, np1, np2, np3;
            if (ks < 15) {
                LDSM_X4(na0, na1, na2, na3, aAddr + (ks + 1) * 32);
                LDSM_X4(np0, np1, np2, np3, bA + (ks + 1) * 32);
            }
            MMA_F16(acc[0][0], acc[0][1], a0, a1, a2, a3, p0, p1);
            MMA_F16(acc[1][0], acc[1][1], a0, a1, a2, a3, p2, p3);
            if (ks < 15) {
                a0 = na0; a1 = na1; a2 = na2; a3 = na3;
                p0 = np0; p1 = np1; p2 = np2; p3 = np3;
            }
        }

        const float t0 = sm.thr[R0];
        const float t1 = sm.thr[R1];
        const float* sq = sm.sqB[s];
        #pragma unroll
        for (int nt = 0; nt < 2; ++nt) {
            const int c = cBase + nt * 8;
            float2 f0 = __half22float2(*(__half2*)&acc[nt][0]);
            float2 f1 = __half22float2(*(__half2*)&acc[nt][1]);
            float v00 = fmaf(-2.f, f0.x, sq[c]);
            float v01 = fmaf(-2.f, f0.y, sq[c + 1]);
            float v10 = fmaf(-2.f, f1.x, sq[c]);
            float v11 = fmaf(-2.f, f1.y, sq[c + 1]);
            if (v00 < t0) { int p = atomicAdd(&sm.cnt[R0], 1);
                sm.cand[R0][p] = ((unsigned long long)mono(v00) << 32) | (unsigned)(j0 + c); }
            if (v01 < t0) { int p = atomicAdd(&sm.cnt[R0], 1);
                sm.cand[R0][p] = ((unsigned long long)mono(v01) << 32) | (unsigned)(j0 + c + 1); }
            if (v10 < t1) { int p = atomicAdd(&sm.cnt[R1], 1);
                sm.cand[R1][p] = ((unsigned long long)mono(v10) << 32) | (unsigned)(j0 + c); }
            if (v11 < t1) { int p = atomicAdd(&sm.cnt[R1], 1);
                sm.cand[R1][p] = ((unsigned long long)mono(v11) << 32) | (unsigned)(j0 + c + 1); }
        }
        __syncthreads();

        if (tid < BMT) {
            int n = sm.cnt[tid];
            if (n) {
                sm.cnt[tid] = 0;
                unsigned long long* bl = sm.best[tid];
                for (int q = 0; q < n; ++q) {
                    unsigned long long key = sm.cand[tid][q];
                    if (key < bl[MST - 1]) {
                        int p = MST - 1;
                        while (p > 0 && bl[p - 1] > key) { bl[p] = bl[p - 1]; --p; }
                        bl[p] = key;
                    }
                }
                sm.thr[tid] = unmono((unsigned)(bl[MST - 1] >> 32));
            }
        }
    }

    if (tid < BMT)
        g_tau[i0 + tid] = unmono((unsigned)(sm.best[tid][MST - 1] >> 32));
}

// ---------------- Kernel S: cyclic symmetric screen, pipelined, 2 CTAs/SM ----------------
struct SmemS {
    __half A[BM][RSB];
    __half B[BN][RSB];
    float sqB[2][BN], tauB[2][BN];
    float sqA[BM], tauA[BM];
    float thr[BM];
    int   cnt[BM];
    unsigned long long best[BM][MS];
    unsigned long long cand[BM][CCAP];
    unsigned long long tval[2][TCAP];
    unsigned char tcol[2][TCAP];
    int tcnt[2];
};

__device__ __forceinline__ void load_BS(SmemS& sm, int sb, int j0, int tid) {
    #pragma unroll
    for (int q = 0; q < 4; ++q) {
        int idx = q * STH + tid;
        int r = idx >> 5, ch = idx & 31;
        unsigned dst = smem_u32(&sm.B[r][ch * 8]);
        const void* src = (const char*)g_fh16 + (((size_t)(j0 + r) * DD) + ch * 8) * 2;
        CP16(dst, src);
    }
    if (tid < 16) {
        unsigned dst = smem_u32(&sm.sqB[sb][tid * 4]);
        CP16(dst, (const void*)(g_sq + j0 + tid * 4));
    } else if (tid < 32) {
        int t = tid - 16;
        unsigned dst = smem_u32(&sm.tauB[sb][t * 4]);
        CP16(dst, (const void*)(g_tau + j0 + t * 4));
    }
}

__global__ void __launch_bounds__(STH, 2) screen_kernel() {
    extern __shared__ char raw[];
    SmemS& sm = *reinterpret_cast<SmemS*>(raw);
    const int tid = threadIdx.x;
    const int lane = tid & 31;
    const int w = tid >> 5;
    const int wr = w >> 2;
    const int wc = w & 3;
    const int bx = blockIdx.x;
    const int it = bx >> 1;
    const int h  = bx & 1;
    const int i0 = it * BM;
    const int NT = (it < 64) ? 65 : 64;
    const int tb = h ? (NT + 1) / 2 : 0;
    const int te = h ? NT : (NT + 1) / 2;

    #pragma unroll
    for (int t = 0; t < 4; ++t) {
        int idx = t * STH + tid;
        int r = idx >> 5, ch = idx & 31;
        unsigned dst = smem_u32(&sm.A[r][ch * 8]);
        const void* src = (const char*)g_fh16 + (((size_t)(i0 + r) * DD) + ch * 8) * 2;
        CP16(dst, src);
    }
    load_BS(sm, tb & 1, ((it + tb) & (NTILE - 1)) * BN, tid);
    CP_COMMIT();

    if (tid < BM) {
        sm.sqA[tid]  = g_sq[i0 + tid];
        float tau = g_tau[i0 + tid];
        sm.tauA[tid] = tau;
        sm.thr[tid]  = tau;
        sm.cnt[tid]  = 0;
        #pragma unroll
        for (int t = 0; t < MS; ++t) sm.best[tid][t] = ULLINF;
    }
    if (tid == 0) { sm.tcnt[0] = 0; sm.tcnt[1] = 0; }
    CP_WAIT(0);
    __syncthreads();

    const unsigned aAddr = smem_u32(&sm.A[wr * 16 + (lane & 15)][0]) + ((lane >> 4) << 4);
    const int rowB = wc * 16 + ((lane >> 4) << 3) + (lane & 7);
    const unsigned bColOff = ((lane >> 3) & 1) << 4;
    const unsigned bAddr = smem_u32(&sm.B[rowB][0]) + bColOff;

    const int R0 = wr * 16 + (lane >> 2);
    const int R1 = R0 + 8;
    const int cBase = wc * 16 + 2 * (lane & 3);

    for (int t = tb; t < te; ++t) {
        const int s = t & 1;
        const int jt = (it + t) & (NTILE - 1);
        const int j0 = jt * BN;
        const bool offdiag = (t != 0);

        // ---- MMA over current B, fragment double-buffered ----
        unsigned acc[2][2];
        acc[0][0] = 0u; acc[0][1] = 0u; acc[1][0] = 0u; acc[1][1] = 0u;
        {
            unsigned a0, a1, a2, a3, p0, p1, p2, p3;
            LDSM_X4(a0, a1, a2, a3, aAddr);
            LDSM_X4(p0, p1, p2, p3, bAddr);
            #pragma unroll
            for (int ks = 0; ks < 16; ++ks) {
                unsigned na0, na1, na2, na3, np0, np1, np2, np3;
                if (ks < 15) {
                    LDSM_X4(na0, na1, na2, na3, aAddr + (ks + 1) * 32);
                    LDSM_X4(np0, np1, np2, np3, bAddr + (ks + 1) * 32);
                }
                MMA_F16(acc[0][0], acc[0][1], a0, a1, a2, a3, p0, p1);
                MMA_F16(acc[1][0], acc[1][1], a0, a1, a2, a3, p2, p3);
                if (ks < 15) {
                    a0 = na0; a1 = na1; a2 = na2; a3 = na3;
                    p0 = np0; p1 = np1; p2 = np2; p3 = np3;
                }
            }
        }
        __syncthreads();   // all B reads done -> safe to overwrite B

        // ---- prefetch next tile (overlaps epilogue + drain/flush) ----
        if (t + 1 < te) {
            load_BS(sm, s ^ 1, ((it + t + 1) & (NTILE - 1)) * BN, tid);
            CP_COMMIT();
        }

        // ---- epilogue: 8 elements/thread, mask-coalesced ----
        const float t0 = sm.thr[R0];
        const float t1 = sm.thr[R1];
        const float sqa0 = sm.sqA[R0];
        const float sqa1 = sm.sqA[R1];
        const float* sq = sm.sqB[s];
        const float* tbv = sm.tauB[s];

        float sv[8];
        {
            float2 f0 = __half22float2(*(__half2*)&acc[0][0]);
            float2 f1 = __half22float2(*(__half2*)&acc[0][1]);
            float2 g0 = __half22float2(*(__half2*)&acc[1][0]);
            float2 g1 = __half22float2(*(__half2*)&acc[1][1]);
            sv[0] = f0.x; sv[1] = f0.y; sv[2] = f1.x; sv[3] = f1.y;
            sv[4] = g0.x; sv[5] = g0.y; sv[6] = g1.x; sv[7] = g1.y;
        }
        float vl[8], wt[8];
        unsigned mL = 0, mT = 0;
        #pragma unroll
        for (int e = 0; e < 8; ++e) {
            const int k = e & 3;
            const int col = cBase + (e >> 2) * 8 + (k & 1);
            const bool hi = (k >= 2);
            vl[e] = fmaf(-2.f, sv[e], sq[col]);
            wt[e] = fmaf(-2.f, sv[e], hi ? sqa1 : sqa0);
            if (vl[e] < (hi ? t1 : t0)) mL |= 1u << e;
            if (wt[e] <= tbv[col])      mT |= 1u << e;
        }
        if (!offdiag) mT = 0;
        if (mL) {
            #pragma unroll
            for (int e = 0; e < 8; ++e) if (mL & (1u << e)) {
                const int k = e & 3;
                const int row = (k >= 2) ? R1 : R0;
                const int col = cBase + (e >> 2) * 8 + (k & 1);
                unsigned long long key = ((unsigned long long)mono(vl[e]) << 32) | (unsigned)(j0 + col);
                int p = atomicAdd(&sm.cnt[row], 1);
                if (p < CCAP) sm.cand[row][p] = key;
                else { int g = atomicAdd(&g_bcnt[i0 + row], 1);
                       if (g < CAP) g_buf[(size_t)(i0 + row) * CAP + g] = key; }
            }
        }
        if (mT) {
            #pragma unroll
            for (int e = 0; e < 8; ++e) if (mT & (1u << e)) {
                const int k = e & 3;
                const int row = (k >= 2) ? R1 : R0;
                const int col = cBase + (e >> 2) * 8 + (k & 1);
                unsigned long long val = ((unsigned long long)mono(wt[e]) << 32) | (unsigned)(i0 + row);
                int p = atomicAdd(&sm.tcnt[s], 1);
                if (p < TCAP) { sm.tval[s][p] = val; sm.tcol[s][p] = (unsigned char)col; }
                else { int g = atomicAdd(&g_bcnt[j0 + col], 1);
                       if (g < CAP) g_buf[(size_t)(j0 + col) * CAP + g] = val; }
            }
        }
        __syncthreads();   // epilogue complete

        // ---- drain staged transpose appends + local flush (overlaps prefetch DMA) ----
        {
            int n = sm.tcnt[s];
            if (n > TCAP) n = TCAP;
            for (int q = tid; q < n; q += STH) {
                int trow = j0 + (int)sm.tcol[s][q];
                int p = atomicAdd(&g_bcnt[trow], 1);
                if (p < CAP) g_buf[(size_t)trow * CAP + p] = sm.tval[s][q];
            }
        }
        if (tid == 0) sm.tcnt[s ^ 1] = 0;
        if (tid < BM) {
            int n = sm.cnt[tid];
            if (n) {
                if (n > CCAP) n = CCAP;
                sm.cnt[tid] = 0;
                unsigned long long* bl = sm.best[tid];
                for (int q = 0; q < n; ++q) {
                    unsigned long long key = sm.cand[tid][q];
                    if (key < bl[MS - 1]) {
                        int p = MS - 1;
                        while (p > 0 && bl[p - 1] > key) { bl[p] = bl[p - 1]; --p; }
                        bl[p] = key;
                    }
                }
                sm.thr[tid] = fminf(sm.tauA[tid], unmono((unsigned)(bl[MS - 1] >> 32)));
            }
        }
        CP_WAIT(0);
        __syncthreads();
    }

    for (int idx = tid; idx < BM * MS; idx += STH) {
        int r = idx / MS, q = idx % MS;
        g_loc[((size_t)(i0 + r) * 2 + h) * MS + q] = sm.best[r][q];
    }
}

// ---------------- Kernel LR: merge locals+buffer -> top-28 -> exact fp32 refine -> top-17 ----------------
__global__ void __launch_bounds__(256) selref_kernel(const float* __restrict__ feats) {
    __shared__ unsigned long long ch[8][32][15];
    const int lane = threadIdx.x & 31;
    const int w = threadIdx.x >> 5;
    const int row = blockIdx.x * 8 + w;

    // --- phase 1: merge 2x local top-24 + buffer into sorted per-lane chunks ---
    unsigned long long* my = ch[w][lane];
    int len = 0;
    const unsigned long long* lp = g_loc + (size_t)row * 2 * MS;
    for (int q = lane; q < 2 * MS; q += 32) {
        unsigned long long key = lp[q];
        int p = len++;
        while (p > 0 && my[p - 1] > key) { my[p] = my[p - 1]; --p; }
        my[p] = key;
    }
    int cnt = g_bcnt[row];
    if (cnt > SCAP) cnt = SCAP;
    const unsigned long long* bp = g_buf + (size_t)row * CAP;
    for (int q = lane; q < cnt; q += 32) {
        unsigned long long key = bp[q];
        int p = len++;
        while (p > 0 && my[p - 1] > key) { my[p] = my[p - 1]; --p; }
        my[p] = key;
    }
    __syncwarp();

    // 28 warp-min extractions; candidate t lands in lane t's register
    unsigned long long myc = ULLINF;
    int ptr = 0;
    for (int sel = 0; sel < RS28; ++sel) {
        unsigned long long hKey = (ptr < len) ? my[ptr] : ULLINF;
        unsigned long long M = hKey;
        #pragma unroll
        for (int o = 16; o; o >>= 1) {
            unsigned long long v = __shfl_xor_sync(0xffffffffu, M, o);
            M = (v < M) ? v : M;
        }
        unsigned b = __ballot_sync(0xffffffffu, hKey == M && M != ULLINF);
        if (b && lane == (__ffs(b) - 1)) ++ptr;
        if (lane == sel) myc = M;
    }

    // --- phase 2: exact fp32 refine of the 28 candidates ---
    const float* base = feats + (size_t)row * DD;
    float4 a0 = *(const float4*)(base + lane * 4);
    float4 a1 = *(const float4*)(base + 128 + lane * 4);
    float own[8] = {a0.x, a0.y, a0.z, a0.w, a1.x, a1.y, a1.z, a1.w};

    unsigned long long mykey = ULLINF;
    for (int t = 0; t < RS28; ++t) {
        unsigned long long ak = __shfl_sync(0xffffffffu, myc, t);
        int j = (ak == ULLINF) ? 0 : (int)(unsigned)(ak & 0xffffffffull);
        const float* nb = feats + (size_t)j * DD;
        float4 b0 = *(const float4*)(nb + lane * 4);
        float4 b1 = *(const float4*)(nb + 128 + lane * 4);
        float p = own[0]*b0.x + own[1]*b0.y + own[2]*b0.z + own[3]*b0.w
                + own[4]*b1.x + own[5]*b1.y + own[6]*b1.z + own[7]*b1.w;
        #pragma unroll
        for (int o = 16; o; o >>= 1) p += __shfl_xor_sync(0xffffffffu, p, o);
        float val = fmaf(-2.f, p, g_sq[j]);
        unsigned long long key = (ak == ULLINF) ? ULLINF
                               : (((unsigned long long)mono(val) << 32) | (unsigned)j);
        if (lane == t) mykey = key;
    }

    int rank = 0;
    #pragma unroll
    for (int s = 0; s < RS28; ++s) {
        unsigned long long ok = __shfl_sync(0xffffffffu, mykey, s);
        rank += (ok < mykey);
    }
    if (lane < RS28 && rank < KSEL && mykey != ULLINF)
        g_best[(size_t)row * KSEL + rank] = mykey;
}

// ---------------- Kernel C: mutual mask + sparse softmax + AV + residual + normalize ----------------
__global__ void fuse_kernel(const float* __restrict__ feats, float* __restrict__ out) {
    int gw = (blockIdx.x * blockDim.x + threadIdx.x) >> 5;
    int lane = threadIdx.x & 31;
    if (gw >= NN) return;
    const int row = gw;
    const float* base = feats + (size_t)row * DD;
    float4 a0 = *(const float4*)(base + lane * 4);
    float4 a1 = *(const float4*)(base + 128 + lane * 4);
    float own[8] = {a0.x, a0.y, a0.z, a0.w, a1.x, a1.y, a1.z, a1.w};

    int my_nbr = -1;
    int cnt = 0;
    #pragma unroll
    for (int t = 0; t < KSEL; ++t) {
        unsigned long long key = g_best[(size_t)row * KSEL + t];
        int j = (int)(unsigned)(key & 0xffffffffull);
        if (j != row && cnt < KK) {
            if (cnt == lane) my_nbr = j;
            cnt++;
        }
    }

    bool found = false;
    if (lane < KK && my_nbr >= 0) {
        #pragma unroll
        for (int t = 0; t < KSEL; ++t) {
            unsigned long long key = g_best[(size_t)my_nbr * KSEL + t];
            if ((int)(unsigned)(key & 0xffffffffull) == row) found = true;
        }
    }
    unsigned mmask = __ballot_sync(0xffffffffu, found) & 0xffffu;

    float m = 1.0f, Z = 1.0f;
    float acc[8];
    #pragma unroll
    for (int e = 0; e < 8; ++e) acc[e] = own[e];

    for (int l = 0; l < KK; ++l) {
        if (!((mmask >> l) & 1u)) continue;
        int j = __shfl_sync(0xffffffffu, my_nbr, l);
        const float* nb = feats + (size_t)j * DD;
        float4 b0 = *(const float4*)(nb + lane * 4);
        float4 b1 = *(const float4*)(nb + 128 + lane * 4);
        float v[8] = {b0.x, b0.y, b0.z, b0.w, b1.x, b1.y, b1.z, b1.w};
        float p = 0.f;
        #pragma unroll
        for (int e = 0; e < 8; ++e) p = fmaf(own[e], v[e], p);
        #pragma unroll
        for (int o = 16; o; o >>= 1) p += __shfl_xor_sync(0xffffffffu, p, o);
        if (p > m) {
            float f = expf(m - p);
            Z = Z * f + 1.0f;
            #pragma unroll
            for (int e = 0; e < 8; ++e) acc[e] = fmaf(acc[e], f, v[e]);
            m = p;
        } else {
            float wgt = expf(p - m);
            Z += wgt;
            #pragma unroll
            for (int e = 0; e < 8; ++e) acc[e] = fmaf(wgt, v[e], acc[e]);
        }
    }

    float invZ = 1.0f / Z;
    float fcm[8];
    float ss = 0.f;
    #pragma unroll
    for (int e = 0; e < 8; ++e) {
        fcm[e] = fmaf(acc[e], invZ, own[e]);
        ss = fmaf(fcm[e], fcm[e], ss);
    }
    #pragma unroll
    for (int o = 16; o; o >>= 1) ss += __shfl_xor_sync(0xffffffffu, ss, o);
    float inv = 1.0f / fmaxf(sqrtf(ss), 1e-12f);

    float* op = out + (size_t)row * DD;
    *(float4*)(op + lane * 4)       = make_float4(fcm[0]*inv, fcm[1]*inv, fcm[2]*inv, fcm[3]*inv);
    *(float4*)(op + 128 + lane * 4) = make_float4(fcm[4]*inv, fcm[5]*inv, fcm[6]*inv, fcm[7]*inv);
}

// ---------------- launch ----------------
extern "C" void kernel_launch(void* const* d_in, const int* in_sizes, int n_in,
                              void* d_out, int out_size) {
    const float* feats = (const float*)d_in[0];
    float* out = (float*)d_out;
    (void)in_sizes; (void)n_in; (void)out_size;

    cudaFuncSetAttribute(thresh_kernel, cudaFuncAttributeMaxDynamicSharedMemorySize,
                         (int)sizeof(SmemT));
    cudaFuncSetAttribute(screen_kernel, cudaFuncAttributeMaxDynamicSharedMemorySize,
                         (int)sizeof(SmemS));

    sq_kernel<<<NN / 8, 256>>>(feats);
    thresh_kernel<<<NTILE * 2, 256, sizeof(SmemT)>>>();
    dummy_kernel<<<1, 32>>>();
    screen_kernel<<<NTILE * 2, STH, sizeof(SmemS)>>>();
    selref_kernel<<<NN / 8, 256>>>(feats);
    fuse_kernel<<<NN / 8, 256>>>(feats, out);
}